// round 12
// baseline (speedup 1.0000x reference)
#include <cuda_runtime.h>
#include <math.h>
#include <stdint.h>

#define BB 2
#define SS 2048
#define HH 1024
#define NH 16
#define HD 64
#define BH 32
#define NROWS 4096

// scratch (static __device__ arrays; no runtime allocation)
__device__ float g_q[(size_t)BH * SS * HD];
__device__ float g_k[(size_t)BH * SS * HD];
__device__ float g_v[(size_t)BH * SS * HD];
__device__ float g_kt[(size_t)BH * HD * SS];      // K transposed: [bh][d][s]
__device__ float g_wt[3 * (size_t)HH * HH];       // Wq,Wk,Wv transposed: [k][n]

typedef unsigned long long u64;

// ---- packed fp32x2 helpers (sm_103a FFMA2) ----
__device__ __forceinline__ u64 bcast2(float x) {
    u64 d; unsigned int u = __float_as_uint(x);
    asm("mov.b64 %0, {%1,%2};" : "=l"(d) : "r"(u), "r"(u));
    return d;
}
__device__ __forceinline__ u64 ffma2(u64 a, u64 b, u64 c) {
    u64 d;
    asm("fma.rn.f32x2 %0, %1, %2, %3;" : "=l"(d) : "l"(a), "l"(b), "l"(c));
    return d;
}
__device__ __forceinline__ float2 unpk(u64 v) {
    unsigned int lo, hi;
    asm("mov.b64 {%0,%1}, %2;" : "=r"(lo), "=r"(hi) : "l"(v));
    return make_float2(__uint_as_float(lo), __uint_as_float(hi));
}
__device__ __forceinline__ float f4c(const float4& v, int i) {
    return i == 0 ? v.x : i == 1 ? v.y : i == 2 ? v.z : v.w;
}

// ---- cp.async helpers ----
__device__ __forceinline__ void cpa16(void* s, const void* g) {
    unsigned int sa = (unsigned int)__cvta_generic_to_shared(s);
    asm volatile("cp.async.ca.shared.global [%0], [%1], 16;" :: "r"(sa), "l"(g));
}
#define CPA_COMMIT  asm volatile("cp.async.commit_group;")
#define CPA_WAIT1   asm volatile("cp.async.wait_group 1;")
#define CPA_WAIT0   asm volatile("cp.async.wait_group 0;")

// ---------------------------------------------------------------------------
// Transpose all three W matrices: g_wt[z][k][n] = W_z[n][k]
// ---------------------------------------------------------------------------
__global__ __launch_bounds__(256) void transpose_w3(
    const float* __restrict__ Wq, const float* __restrict__ Wk,
    const float* __restrict__ Wv, float* __restrict__ outp)
{
    __shared__ float t[32][33];
    const int z = blockIdx.z;
    const float* in = z == 0 ? Wq : z == 1 ? Wk : Wv;
    float* op = outp + (size_t)z * HH * HH;
    const int x0 = blockIdx.x * 32, y0 = blockIdx.y * 32;
    const int x = threadIdx.x, y = threadIdx.y;   // 32 x 8
    for (int i = y; i < 32; i += 8) t[i][x] = in[(size_t)(y0 + i) * HH + x0 + x];
    __syncthreads();
    for (int i = y; i < 32; i += 8) op[(size_t)(x0 + i) * HH + y0 + x] = t[x][i];
}

// ---------------------------------------------------------------------------
// Transpose K: [bh][s][d] -> [bh][d][s]
// ---------------------------------------------------------------------------
__global__ __launch_bounds__(256) void transpose_k(
    const float* __restrict__ in, float* __restrict__ outp)
{
    __shared__ float t[32][33];
    const int bh = blockIdx.z;
    const int s0 = blockIdx.x * 32;
    const int d0 = blockIdx.y * 32;
    const int x = threadIdx.x, y = threadIdx.y;   // 32 x 8
    const float* ip = in + ((size_t)bh * SS + s0) * HD + d0;
    for (int i = y; i < 32; i += 8) t[i][x] = ip[(size_t)i * HD + x];
    __syncthreads();
    float* op = outp + ((size_t)bh * HD + d0) * SS + s0;
    for (int i = y; i < 32; i += 8) op[(size_t)i * SS + x] = t[x][i];
}

// ---------------------------------------------------------------------------
// Fused QKV projection GEMM: out = X @ W^T + b, scattered to [bh][s][d].
// zbase+blockIdx.z -> zmap {k,q,v} so the k projection can be launched alone
// first (transpose_k forks off it). Tile 64x128, BK=32, 4x16 FFMA2 micro.
// ---------------------------------------------------------------------------
#define APAD 36
#define PROJ_STAGE (64 * APAD + 32 * 128)    // 6400 floats per stage
#define PROJ_SMEM (2 * PROJ_STAGE * 4)       // 51.2 KB

__global__ __launch_bounds__(128, 4) void proj_kernel(
    const float* __restrict__ Xq, const float* __restrict__ Xk,
    const float* __restrict__ Xv, const float* __restrict__ Wt3,
    const float* __restrict__ bq, const float* __restrict__ bk,
    const float* __restrict__ bv,
    float* __restrict__ oq, float* __restrict__ ok, float* __restrict__ ov,
    int zbase)
{
    extern __shared__ float sm[];
    const int zmap[3] = {1, 0, 2};             // launch order: k, then q,v
    const int z = zmap[zbase + blockIdx.z];
    const float* X    = z == 0 ? Xq : z == 1 ? Xk : Xv;
    const float* Wt   = Wt3 + (size_t)z * HH * HH;
    const float* bias = z == 0 ? bq : z == 1 ? bk : bv;
    float* outp       = z == 0 ? oq : z == 1 ? ok : ov;

    const int tid = threadIdx.x;
    const int tx = tid & 7;            // col base tx*4, chunks +0,+32,+64,+96
    const int ty = tid >> 3;           // 0..15; rows i*16+ty
    const int i0 = blockIdx.y * 64;
    const int j0 = blockIdx.x * 128;

    auto prefetch = [&](int k0, int buf) {
        float* As = sm + buf * PROJ_STAGE;
        float* Bs = As + 64 * APAD;
#pragma unroll
        for (int e = 0; e < 4; e++) {
            int f = e * 128 + tid;
            int r = f >> 3, c4 = f & 7;
            cpa16(&As[r * APAD + c4 * 4], X + (size_t)(i0 + r) * HH + k0 + c4 * 4);
        }
#pragma unroll
        for (int e = 0; e < 8; e++) {
            int f = e * 128 + tid;
            int k = f >> 5, c = f & 31;
            cpa16(&Bs[k * 128 + c * 4], Wt + (size_t)(k0 + k) * HH + j0 + c * 4);
        }
        CPA_COMMIT;
    };

    u64 acc[4][8];
#pragma unroll
    for (int i = 0; i < 4; i++)
#pragma unroll
        for (int j = 0; j < 8; j++) acc[i][j] = 0ull;

    prefetch(0, 0);

    for (int it = 0; it < 32; it++) {
        if (it < 31) { prefetch((it + 1) * 32, (it + 1) & 1); CPA_WAIT1; }
        else         { CPA_WAIT0; }
        __syncthreads();
        const float* As = sm + (it & 1) * PROJ_STAGE;
        const float* Bs = As + 64 * APAD;
#pragma unroll
        for (int k4 = 0; k4 < 8; k4++) {
            float4 aq[4];
#pragma unroll
            for (int i = 0; i < 4; i++)
                aq[i] = *(const float4*)&As[(i * 16 + ty) * APAD + k4 * 4];
#pragma unroll
            for (int dd = 0; dd < 4; dd++) {
                const float* bp = &Bs[(k4 * 4 + dd) * 128 + tx * 4];
                ulonglong2 b0 = *(const ulonglong2*)bp;
                ulonglong2 b1 = *(const ulonglong2*)(bp + 32);
                ulonglong2 b2 = *(const ulonglong2*)(bp + 64);
                ulonglong2 b3 = *(const ulonglong2*)(bp + 96);
#pragma unroll
                for (int i = 0; i < 4; i++) {
                    u64 ap = bcast2(f4c(aq[i], dd));
                    acc[i][0] = ffma2(ap, b0.x, acc[i][0]);
                    acc[i][1] = ffma2(ap, b0.y, acc[i][1]);
                    acc[i][2] = ffma2(ap, b1.x, acc[i][2]);
                    acc[i][3] = ffma2(ap, b1.y, acc[i][3]);
                    acc[i][4] = ffma2(ap, b2.x, acc[i][4]);
                    acc[i][5] = ffma2(ap, b2.y, acc[i][5]);
                    acc[i][6] = ffma2(ap, b3.x, acc[i][6]);
                    acc[i][7] = ffma2(ap, b3.y, acc[i][7]);
                }
            }
        }
        __syncthreads();
    }

#pragma unroll
    for (int c = 0; c < 4; c++) {
        const int col = j0 + tx * 4 + c * 32;
        const int h = col >> 6, d = col & 63;
        float4 bb = *(const float4*)(bias + col);
#pragma unroll
        for (int i = 0; i < 4; i++) {
            int r = i0 + i * 16 + ty;
            int b = r >> 11, s = r & 2047;
            float2 p0 = unpk(acc[i][c * 2]), p1 = unpk(acc[i][c * 2 + 1]);
            float4 o4 = make_float4(p0.x + bb.x, p0.y + bb.y, p1.x + bb.z, p1.y + bb.w);
            *(float4*)(outp + (((size_t)(b * NH + h)) * SS + s) * HD + d) = o4;
        }
    }
}

// ---------------------------------------------------------------------------
// Score GEMM: wout[bh][i][j] = 0.25 * sum_d q[i,d]*k[j,d].
// bh = bh0 + blockIdx.z (quartered for pipelined launch). 4x16 micro-tile.
// ---------------------------------------------------------------------------
#define QPAD 68
#define KSTAGE (64 * 128)
#define SCORE_SMEM ((128 * QPAD + 2 * KSTAGE) * 4)

__global__ __launch_bounds__(256, 2) void score_kernel(float* __restrict__ wout,
                                                       int bh0)
{
    extern __shared__ float sm[];
    float* Qs = sm;                       // [128][QPAD]
    float* Kbuf = sm + 128 * QPAD;        // 2 x [64][128]
    const int tid = threadIdx.x;
    const int tx = tid & 7;               // col base tx*4, chunks +0,+32,+64,+96
    const int ty = tid >> 3;              // 0..31; rows i*32+ty
    const int bh = bh0 + blockIdx.z;
    const int i0 = blockIdx.y * 128;
    const int jb0 = blockIdx.x * 4;

    const float* Qp = g_q + ((size_t)bh * SS + i0) * HD;
    const float* Ktp = g_kt + (size_t)bh * HD * SS;

#pragma unroll
    for (int e = 0; e < 8; e++) {
        int f = e * 256 + tid;
        int r = f >> 4, c4 = f & 15;
        cpa16(&Qs[r * QPAD + c4 * 4], Qp + (size_t)r * HD + c4 * 4);
    }
    CPA_COMMIT;

    auto prefetchK = [&](int j0, int buf) {
        float* Ks = Kbuf + buf * KSTAGE;
#pragma unroll
        for (int e = 0; e < 8; e++) {
            int f = e * 256 + tid;
            int d = f >> 5, c = f & 31;
            cpa16(&Ks[d * 128 + c * 4], Ktp + (size_t)d * SS + j0 + c * 4);
        }
        CPA_COMMIT;
    };
    prefetchK(jb0 * 128, 0);

    for (int jt = 0; jt < 4; jt++) {
        const int j0 = (jb0 + jt) * 128;
        if (jt < 3) { prefetchK(j0 + 128, (jt + 1) & 1); CPA_WAIT1; }
        else        { CPA_WAIT0; }
        __syncthreads();
        const float* Ks = Kbuf + (jt & 1) * KSTAGE;

        u64 acc[4][8];
#pragma unroll
        for (int i = 0; i < 4; i++)
#pragma unroll
            for (int j = 0; j < 8; j++) acc[i][j] = 0ull;

#pragma unroll 4
        for (int d4 = 0; d4 < 16; d4++) {
            float4 aq[4];
#pragma unroll
            for (int i = 0; i < 4; i++)
                aq[i] = *(const float4*)&Qs[(i * 32 + ty) * QPAD + d4 * 4];
#pragma unroll
            for (int dd = 0; dd < 4; dd++) {
                const float* bp = &Ks[(d4 * 4 + dd) * 128 + tx * 4];
                ulonglong2 b0 = *(const ulonglong2*)bp;
                ulonglong2 b1 = *(const ulonglong2*)(bp + 32);
                ulonglong2 b2 = *(const ulonglong2*)(bp + 64);
                ulonglong2 b3 = *(const ulonglong2*)(bp + 96);
#pragma unroll
                for (int i = 0; i < 4; i++) {
                    u64 ap = bcast2(f4c(aq[i], dd));
                    acc[i][0] = ffma2(ap, b0.x, acc[i][0]);
                    acc[i][1] = ffma2(ap, b0.y, acc[i][1]);
                    acc[i][2] = ffma2(ap, b1.x, acc[i][2]);
                    acc[i][3] = ffma2(ap, b1.y, acc[i][3]);
                    acc[i][4] = ffma2(ap, b2.x, acc[i][4]);
                    acc[i][5] = ffma2(ap, b2.y, acc[i][5]);
                    acc[i][6] = ffma2(ap, b3.x, acc[i][6]);
                    acc[i][7] = ffma2(ap, b3.y, acc[i][7]);
                }
            }
        }

#pragma unroll
        for (int i = 0; i < 4; i++) {
            float* op = wout + ((size_t)bh * SS + i0 + i * 32 + ty) * SS + j0 + tx * 4;
#pragma unroll
            for (int c = 0; c < 4; c++) {
                float2 p0 = unpk(acc[i][c * 2]), p1 = unpk(acc[i][c * 2 + 1]);
                float4 o4 = make_float4(p0.x * 0.25f, p0.y * 0.25f,
                                        p1.x * 0.25f, p1.y * 0.25f);
                *(float4*)(op + c * 32) = o4;
            }
        }
        __syncthreads();
    }
}

// ---------------------------------------------------------------------------
// Row softmax + threshold prune + L1 renorm, in place (exact fp32 path).
// row = row0 + ... (quartered). One warp per row; 2048 floats in 64 regs/lane.
// ---------------------------------------------------------------------------
__global__ __launch_bounds__(256) void softmax_kernel(
    const unsigned char* __restrict__ mask, float* __restrict__ w, int row0)
{
    const int lane = threadIdx.x & 31;
    const size_t row = (size_t)row0 + (size_t)blockIdx.x * 8 + (threadIdx.x >> 5);
    const int b = (int)(row >> 15);
    float4* rp = (float4*)(w + row * SS);
    const uchar4* mp = (const uchar4*)(mask + (size_t)b * SS);

    float x[64];
    float mx = -3.0e38f;
#pragma unroll
    for (int v = 0; v < 16; v++) {
        float4 t = rp[lane + v * 32];
        uchar4 m = mp[lane + v * 32];
        x[v * 4 + 0] = m.x ? -1e30f : t.x;
        x[v * 4 + 1] = m.y ? -1e30f : t.y;
        x[v * 4 + 2] = m.z ? -1e30f : t.z;
        x[v * 4 + 3] = m.w ? -1e30f : t.w;
    }
#pragma unroll
    for (int i = 0; i < 64; i++) mx = fmaxf(mx, x[i]);
#pragma unroll
    for (int o = 16; o; o >>= 1) mx = fmaxf(mx, __shfl_xor_sync(0xffffffffu, mx, o));

    float z = 0.f;
#pragma unroll
    for (int i = 0; i < 64; i++) {
        float e = __expf(x[i] - mx);
        x[i] = e;
        z += e;
    }
#pragma unroll
    for (int o = 16; o; o >>= 1) z += __shfl_xor_sync(0xffffffffu, z, o);

    const float cut = 0.01f * z;
    float sk = 0.f;
#pragma unroll
    for (int i = 0; i < 64; i++)
        if (x[i] >= cut) sk += x[i];
#pragma unroll
    for (int o = 16; o; o >>= 1) sk += __shfl_xor_sync(0xffffffffu, sk, o);
    const float inv = sk > 0.f ? 1.f / sk : 0.f;

#pragma unroll
    for (int v = 0; v < 16; v++) {
        float4 o4;
        o4.x = x[v * 4 + 0] >= cut ? x[v * 4 + 0] * inv : 0.f;
        o4.y = x[v * 4 + 1] >= cut ? x[v * 4 + 1] * inv : 0.f;
        o4.z = x[v * 4 + 2] >= cut ? x[v * 4 + 2] * inv : 0.f;
        o4.w = x[v * 4 + 3] >= cut ? x[v * 4 + 3] * inv : 0.f;
        rp[lane + v * 32] = o4;
    }
}

// ---------------------------------------------------------------------------
// PV GEMM: out[b][s][h*64+d] = sum_j W[bh][i][j] * V[bh][j][d].
// bh = bh0 + blockIdx.y (quartered). Tile 128x64, k-chunk 32, 4x16 micro.
// ---------------------------------------------------------------------------
#define WPAD 36
#define PV_STAGE (128 * WPAD + 32 * 64)     // 6656 floats per stage
#define PV_SMEM (2 * PV_STAGE * 4)          // 53.2 KB

__global__ __launch_bounds__(128, 4) void pv_kernel(
    const float* __restrict__ wts, float* __restrict__ outp, int bh0)
{
    extern __shared__ float psm[];
    const int tid = threadIdx.x;
    const int tx = tid & 3;            // col base tx*4, chunks +0,+16,+32,+48
    const int ty = tid >> 2;           // 0..31; rows i*32+ty
    const int bh = bh0 + blockIdx.y;
    const int b = bh >> 4, h = bh & 15;
    const int i0 = blockIdx.x * 128;
    const float* Wp = wts + ((size_t)bh * SS + i0) * SS;
    const float* Vp = g_v + (size_t)bh * SS * HD;

    auto prefetch = [&](int kc, int buf) {
        float* Wt = psm + buf * PV_STAGE;
        float* Vt = Wt + 128 * WPAD;
#pragma unroll
        for (int e = 0; e < 8; e++) {
            int f = e * 128 + tid;
            int r = f >> 3, c4 = f & 7;
            cpa16(&Wt[r * WPAD + c4 * 4], Wp + (size_t)r * SS + kc + c4 * 4);
        }
#pragma unroll
        for (int e = 0; e < 4; e++) {
            int f = e * 128 + tid;
            int j = f >> 4, c4 = f & 15;
            cpa16(&Vt[j * 64 + c4 * 4], Vp + (size_t)(kc + j) * HD + c4 * 4);
        }
        CPA_COMMIT;
    };

    u64 acc[4][8];
#pragma unroll
    for (int i = 0; i < 4; i++)
#pragma unroll
        for (int j = 0; j < 8; j++) acc[i][j] = 0ull;

    prefetch(0, 0);

    for (int it = 0; it < 64; it++) {
        if (it < 63) { prefetch((it + 1) * 32, (it + 1) & 1); CPA_WAIT1; }
        else         { CPA_WAIT0; }
        __syncthreads();
        const float* Wt = psm + (it & 1) * PV_STAGE;
        const float* Vt = Wt + 128 * WPAD;
#pragma unroll
        for (int k4 = 0; k4 < 8; k4++) {
            float4 aw[4];
#pragma unroll
            for (int i = 0; i < 4; i++)
                aw[i] = *(const float4*)&Wt[(i * 32 + ty) * WPAD + k4 * 4];
#pragma unroll
            for (int dd = 0; dd < 4; dd++) {
                const float* bp = &Vt[(k4 * 4 + dd) * 64 + tx * 4];
                ulonglong2 b0 = *(const ulonglong2*)bp;
                ulonglong2 b1 = *(const ulonglong2*)(bp + 16);
                ulonglong2 b2 = *(const ulonglong2*)(bp + 32);
                ulonglong2 b3 = *(const ulonglong2*)(bp + 48);
#pragma unroll
                for (int i = 0; i < 4; i++) {
                    u64 ap = bcast2(f4c(aw[i], dd));
                    acc[i][0] = ffma2(ap, b0.x, acc[i][0]);
                    acc[i][1] = ffma2(ap, b0.y, acc[i][1]);
                    acc[i][2] = ffma2(ap, b1.x, acc[i][2]);
                    acc[i][3] = ffma2(ap, b1.y, acc[i][3]);
                    acc[i][4] = ffma2(ap, b2.x, acc[i][4]);
                    acc[i][5] = ffma2(ap, b2.y, acc[i][5]);
                    acc[i][6] = ffma2(ap, b3.x, acc[i][6]);
                    acc[i][7] = ffma2(ap, b3.y, acc[i][7]);
                }
            }
        }
        __syncthreads();
    }

#pragma unroll
    for (int i = 0; i < 4; i++) {
        int s = i0 + i * 32 + ty;
        float* op = outp + ((size_t)b * SS + s) * HH + h * HD + tx * 4;
#pragma unroll
        for (int c = 0; c < 4; c++) {
            float2 p0 = unpk(acc[i][c * 2]), p1 = unpk(acc[i][c * 2 + 1]);
            float4 o4 = make_float4(p0.x, p0.y, p1.x, p1.y);
            *(float4*)(op + c * 16) = o4;
        }
    }
}

// ---------------------------------------------------------------------------
// Orchestration: fork-join pipeline. Softmax quarters run on a side stream,
// overlapping the (fma-bound) score/pv GEMMs with the (DRAM-bound) softmax.
// Dependency graph: proj_k -> tk (s1) -> score Qi -> softmax Qi (s1) -> pv Qi.
// ---------------------------------------------------------------------------
extern "C" void kernel_launch(void* const* d_in, const int* in_sizes, int n_in,
                              void* d_out, int out_size)
{
    const float* query = (const float*)d_in[0];
    const float* key   = (const float*)d_in[1];
    const float* value = (const float*)d_in[2];
    const unsigned char* mask = (const unsigned char*)d_in[3];
    const float* Wq = (const float*)d_in[4];
    const float* bq = (const float*)d_in[5];
    const float* Wk = (const float*)d_in[6];
    const float* bk = (const float*)d_in[7];
    const float* Wv = (const float*)d_in[8];
    const float* bv = (const float*)d_in[9];

    float* outp = (float*)d_out;                        // [B,S,H]
    float* wts  = outp + (size_t)BB * SS * HH;          // [B,h,S,S]

    float *gq, *gk, *gv, *gkt, *gwt;
    cudaGetSymbolAddress((void**)&gq, g_q);
    cudaGetSymbolAddress((void**)&gk, g_k);
    cudaGetSymbolAddress((void**)&gv, g_v);
    cudaGetSymbolAddress((void**)&gkt, g_kt);
    cudaGetSymbolAddress((void**)&gwt, g_wt);

    cudaFuncSetAttribute(proj_kernel, cudaFuncAttributeMaxDynamicSharedMemorySize,
                         PROJ_SMEM);
    cudaFuncSetAttribute(score_kernel, cudaFuncAttributeMaxDynamicSharedMemorySize,
                         SCORE_SMEM);
    cudaFuncSetAttribute(pv_kernel, cudaFuncAttributeMaxDynamicSharedMemorySize,
                         PV_SMEM);

    // side stream + events (created per call; a handful leak over the harness's
    // 2-3 calls — no device-memory allocation involved)
    cudaStream_t s1;
    cudaStreamCreateWithFlags(&s1, cudaStreamNonBlocking);
    cudaEvent_t e_pk, e_tk, e_s[4], e_m[4];
    cudaEventCreateWithFlags(&e_pk, cudaEventDisableTiming);
    cudaEventCreateWithFlags(&e_tk, cudaEventDisableTiming);
    for (int q = 0; q < 4; q++) {
        cudaEventCreateWithFlags(&e_s[q], cudaEventDisableTiming);
        cudaEventCreateWithFlags(&e_m[q], cudaEventDisableTiming);
    }

    dim3 tb(32, 8);

    // weight transposes (needed by all projections)
    transpose_w3<<<dim3(32, 32, 3), tb>>>(Wq, Wk, Wv, gwt);

    // K projection first; fork transpose_k onto s1 under the q/v projection
    proj_kernel<<<dim3(HH / 128, NROWS / 64, 1), 128, PROJ_SMEM>>>(
        query, key, value, gwt, bq, bk, bv, gq, gk, gv, 0);
    cudaEventRecord(e_pk, 0);
    proj_kernel<<<dim3(HH / 128, NROWS / 64, 2), 128, PROJ_SMEM>>>(
        query, key, value, gwt, bq, bk, bv, gq, gk, gv, 1);

    cudaStreamWaitEvent(s1, e_pk, 0);
    transpose_k<<<dim3(SS / 32, HD / 32, BH), tb, 0, s1>>>(gk, gkt);
    cudaEventRecord(e_tk, s1);
    cudaStreamWaitEvent(0, e_tk, 0);

    // pipelined quarters: score Qi (main) -> softmax Qi (s1) -> pv Qi (main)
    for (int q = 0; q < 4; q++) {
        score_kernel<<<dim3(SS / 128 / 4, SS / 128, 8), 256, SCORE_SMEM>>>(
            wts, q * 8);
        cudaEventRecord(e_s[q], 0);
        cudaStreamWaitEvent(s1, e_s[q], 0);
        softmax_kernel<<<(8 * SS) / 8, 256, 0, s1>>>(mask, wts, q * 8 * SS);
        cudaEventRecord(e_m[q], s1);
    }
    for (int q = 0; q < 4; q++) {
        cudaStreamWaitEvent(0, e_m[q], 0);
        pv_kernel<<<dim3(SS / 128, 8), 128, PV_SMEM>>>(wts, outp, q * 8);
    }
    // main stream waited on e_m[3] -> all side-stream work joins the graph
}

// round 13
// speedup vs baseline: 1.2021x; 1.2021x over previous
#include <cuda_runtime.h>
#include <math.h>
#include <stdint.h>

#define BB 2
#define SS 2048
#define HH 1024
#define NH 16
#define HD 64
#define BH 32
#define NROWS 4096

// scratch (static __device__ arrays; no runtime allocation)
__device__ float g_q[(size_t)BH * SS * HD];
__device__ float g_k[(size_t)BH * SS * HD];
__device__ float g_v[(size_t)BH * SS * HD];
__device__ float g_kt[(size_t)BH * HD * SS];      // K transposed: [bh][d][s]
__device__ float g_wt[3 * (size_t)HH * HH];       // Wq,Wk,Wv transposed: [k][n]
__device__ float4 g_stats[(size_t)BH * SS];       // per row: (mx, cut, inv, 0)
__device__ int    g_cnt[BH * 16];                 // strip arrival counters (self-reset)

typedef unsigned long long u64;

// ---- packed fp32x2 helpers (sm_103a FFMA2) ----
__device__ __forceinline__ u64 bcast2(float x) {
    u64 d; unsigned int u = __float_as_uint(x);
    asm("mov.b64 %0, {%1,%2};" : "=l"(d) : "r"(u), "r"(u));
    return d;
}
__device__ __forceinline__ u64 ffma2(u64 a, u64 b, u64 c) {
    u64 d;
    asm("fma.rn.f32x2 %0, %1, %2, %3;" : "=l"(d) : "l"(a), "l"(b), "l"(c));
    return d;
}
__device__ __forceinline__ float2 unpk(u64 v) {
    unsigned int lo, hi;
    asm("mov.b64 {%0,%1}, %2;" : "=r"(lo), "=r"(hi) : "l"(v));
    return make_float2(__uint_as_float(lo), __uint_as_float(hi));
}
__device__ __forceinline__ float f4c(const float4& v, int i) {
    return i == 0 ? v.x : i == 1 ? v.y : i == 2 ? v.z : v.w;
}

// ---- cp.async helpers ----
__device__ __forceinline__ void cpa16(void* s, const void* g) {
    unsigned int sa = (unsigned int)__cvta_generic_to_shared(s);
    asm volatile("cp.async.ca.shared.global [%0], [%1], 16;" :: "r"(sa), "l"(g));
}
#define CPA_COMMIT  asm volatile("cp.async.commit_group;")
#define CPA_WAIT1   asm volatile("cp.async.wait_group 1;")
#define CPA_WAIT0   asm volatile("cp.async.wait_group 0;")

// ---------------------------------------------------------------------------
// Transpose all three W matrices: g_wt[z][k][n] = W_z[n][k]
// ---------------------------------------------------------------------------
__global__ __launch_bounds__(256) void transpose_w3(
    const float* __restrict__ Wq, const float* __restrict__ Wk,
    const float* __restrict__ Wv, float* __restrict__ outp)
{
    __shared__ float t[32][33];
    const int z = blockIdx.z;
    const float* in = z == 0 ? Wq : z == 1 ? Wk : Wv;
    float* op = outp + (size_t)z * HH * HH;
    const int x0 = blockIdx.x * 32, y0 = blockIdx.y * 32;
    const int x = threadIdx.x, y = threadIdx.y;   // 32 x 8
    for (int i = y; i < 32; i += 8) t[i][x] = in[(size_t)(y0 + i) * HH + x0 + x];
    __syncthreads();
    for (int i = y; i < 32; i += 8) op[(size_t)(x0 + i) * HH + y0 + x] = t[x][i];
}

// ---------------------------------------------------------------------------
// Transpose K: [bh][s][d] -> [bh][d][s]
// ---------------------------------------------------------------------------
__global__ __launch_bounds__(256) void transpose_k(
    const float* __restrict__ in, float* __restrict__ outp)
{
    __shared__ float t[32][33];
    const int bh = blockIdx.z;
    const int s0 = blockIdx.x * 32;
    const int d0 = blockIdx.y * 32;
    const int x = threadIdx.x, y = threadIdx.y;   // 32 x 8
    const float* ip = in + ((size_t)bh * SS + s0) * HD + d0;
    for (int i = y; i < 32; i += 8) t[i][x] = ip[(size_t)i * HD + x];
    __syncthreads();
    float* op = outp + ((size_t)bh * HD + d0) * SS + s0;
    for (int i = y; i < 32; i += 8) op[(size_t)i * SS + x] = t[x][i];
}

// ---------------------------------------------------------------------------
// Fused QKV projection GEMM (grid.z selects q/k/v): out = X @ W^T + b,
// scattered to [bh][s][d]. Tile 64(M)x128(N), BK=32, 4x16 FFMA2 micro-tile.
// ---------------------------------------------------------------------------
#define APAD 36
#define PROJ_STAGE (64 * APAD + 32 * 128)    // 6400 floats per stage
#define PROJ_SMEM (2 * PROJ_STAGE * 4)       // 51.2 KB

__global__ __launch_bounds__(128, 4) void proj_kernel(
    const float* __restrict__ Xq, const float* __restrict__ Xk,
    const float* __restrict__ Xv, const float* __restrict__ Wt3,
    const float* __restrict__ bq, const float* __restrict__ bk,
    const float* __restrict__ bv,
    float* __restrict__ oq, float* __restrict__ ok, float* __restrict__ ov)
{
    extern __shared__ float sm[];
    const int z = blockIdx.z;
    const float* X    = z == 0 ? Xq : z == 1 ? Xk : Xv;
    const float* Wt   = Wt3 + (size_t)z * HH * HH;
    const float* bias = z == 0 ? bq : z == 1 ? bk : bv;
    float* outp       = z == 0 ? oq : z == 1 ? ok : ov;

    const int tid = threadIdx.x;
    const int tx = tid & 7;            // col base tx*4, chunks +0,+32,+64,+96
    const int ty = tid >> 3;           // 0..15; rows i*16+ty
    const int i0 = blockIdx.y * 64;
    const int j0 = blockIdx.x * 128;

    auto prefetch = [&](int k0, int buf) {
        float* As = sm + buf * PROJ_STAGE;
        float* Bs = As + 64 * APAD;
#pragma unroll
        for (int e = 0; e < 4; e++) {
            int f = e * 128 + tid;
            int r = f >> 3, c4 = f & 7;
            cpa16(&As[r * APAD + c4 * 4], X + (size_t)(i0 + r) * HH + k0 + c4 * 4);
        }
#pragma unroll
        for (int e = 0; e < 8; e++) {
            int f = e * 128 + tid;
            int k = f >> 5, c = f & 31;
            cpa16(&Bs[k * 128 + c * 4], Wt + (size_t)(k0 + k) * HH + j0 + c * 4);
        }
        CPA_COMMIT;
    };

    u64 acc[4][8];
#pragma unroll
    for (int i = 0; i < 4; i++)
#pragma unroll
        for (int j = 0; j < 8; j++) acc[i][j] = 0ull;

    prefetch(0, 0);

    for (int it = 0; it < 32; it++) {
        if (it < 31) { prefetch((it + 1) * 32, (it + 1) & 1); CPA_WAIT1; }
        else         { CPA_WAIT0; }
        __syncthreads();
        const float* As = sm + (it & 1) * PROJ_STAGE;
        const float* Bs = As + 64 * APAD;
#pragma unroll
        for (int k4 = 0; k4 < 8; k4++) {
            float4 aq[4];
#pragma unroll
            for (int i = 0; i < 4; i++)
                aq[i] = *(const float4*)&As[(i * 16 + ty) * APAD + k4 * 4];
#pragma unroll
            for (int dd = 0; dd < 4; dd++) {
                const float* bp = &Bs[(k4 * 4 + dd) * 128 + tx * 4];
                ulonglong2 b0 = *(const ulonglong2*)bp;
                ulonglong2 b1 = *(const ulonglong2*)(bp + 32);
                ulonglong2 b2 = *(const ulonglong2*)(bp + 64);
                ulonglong2 b3 = *(const ulonglong2*)(bp + 96);
#pragma unroll
                for (int i = 0; i < 4; i++) {
                    u64 ap = bcast2(f4c(aq[i], dd));
                    acc[i][0] = ffma2(ap, b0.x, acc[i][0]);
                    acc[i][1] = ffma2(ap, b0.y, acc[i][1]);
                    acc[i][2] = ffma2(ap, b1.x, acc[i][2]);
                    acc[i][3] = ffma2(ap, b1.y, acc[i][3]);
                    acc[i][4] = ffma2(ap, b2.x, acc[i][4]);
                    acc[i][5] = ffma2(ap, b2.y, acc[i][5]);
                    acc[i][6] = ffma2(ap, b3.x, acc[i][6]);
                    acc[i][7] = ffma2(ap, b3.y, acc[i][7]);
                }
            }
        }
        __syncthreads();
    }

#pragma unroll
    for (int c = 0; c < 4; c++) {
        const int col = j0 + tx * 4 + c * 32;
        const int h = col >> 6, d = col & 63;
        float4 bb = *(const float4*)(bias + col);
#pragma unroll
        for (int i = 0; i < 4; i++) {
            int r = i0 + i * 16 + ty;
            int b = r >> 11, s = r & 2047;
            float2 p0 = unpk(acc[i][c * 2]), p1 = unpk(acc[i][c * 2 + 1]);
            float4 o4 = make_float4(p0.x + bb.x, p0.y + bb.y, p1.x + bb.z, p1.y + bb.w);
            *(float4*)(outp + (((size_t)(b * NH + h)) * SS + s) * HD + d) = o4;
        }
    }
}

// ---------------------------------------------------------------------------
// Score GEMM + in-line row stats. wout[bh][i][j] = 0.25 * sum_d q[i,d]*k[j,d].
// The LAST of the 4 sibling blocks per 128-row strip (atomic counter) re-reads
// the strip (L2-hot) and computes per-row (mx, cut, inv) -> g_stats. Counter
// self-resets for graph replays.
// ---------------------------------------------------------------------------
#define QPAD 68
#define KSTAGE (64 * 128)
#define SCORE_SMEM ((128 * QPAD + 2 * KSTAGE) * 4)

__global__ __launch_bounds__(256, 2) void score_kernel(
    float* __restrict__ wout, const unsigned char* __restrict__ mask)
{
    extern __shared__ float sm[];
    float* Qs = sm;                       // [128][QPAD]
    float* Kbuf = sm + 128 * QPAD;        // 2 x [64][128]
    __shared__ int s_last;
    const int tid = threadIdx.x;
    const int tx = tid & 7;               // col base tx*4, chunks +0,+32,+64,+96
    const int ty = tid >> 3;              // 0..31; rows i*32+ty
    const int bh = blockIdx.z;
    const int i0 = blockIdx.y * 128;
    const int jb0 = blockIdx.x * 4;

    const float* Qp = g_q + ((size_t)bh * SS + i0) * HD;
    const float* Ktp = g_kt + (size_t)bh * HD * SS;

#pragma unroll
    for (int e = 0; e < 8; e++) {
        int f = e * 256 + tid;
        int r = f >> 4, c4 = f & 15;
        cpa16(&Qs[r * QPAD + c4 * 4], Qp + (size_t)r * HD + c4 * 4);
    }
    CPA_COMMIT;

    auto prefetchK = [&](int j0, int buf) {
        float* Ks = Kbuf + buf * KSTAGE;
#pragma unroll
        for (int e = 0; e < 8; e++) {
            int f = e * 256 + tid;
            int d = f >> 5, c = f & 31;
            cpa16(&Ks[d * 128 + c * 4], Ktp + (size_t)d * SS + j0 + c * 4);
        }
        CPA_COMMIT;
    };
    prefetchK(jb0 * 128, 0);

    for (int jt = 0; jt < 4; jt++) {
        const int j0 = (jb0 + jt) * 128;
        if (jt < 3) { prefetchK(j0 + 128, (jt + 1) & 1); CPA_WAIT1; }
        else        { CPA_WAIT0; }
        __syncthreads();
        const float* Ks = Kbuf + (jt & 1) * KSTAGE;

        u64 acc[4][8];
#pragma unroll
        for (int i = 0; i < 4; i++)
#pragma unroll
            for (int j = 0; j < 8; j++) acc[i][j] = 0ull;

#pragma unroll 4
        for (int d4 = 0; d4 < 16; d4++) {
            float4 aq[4];
#pragma unroll
            for (int i = 0; i < 4; i++)
                aq[i] = *(const float4*)&Qs[(i * 32 + ty) * QPAD + d4 * 4];
#pragma unroll
            for (int dd = 0; dd < 4; dd++) {
                const float* bp = &Ks[(d4 * 4 + dd) * 128 + tx * 4];
                ulonglong2 b0 = *(const ulonglong2*)bp;
                ulonglong2 b1 = *(const ulonglong2*)(bp + 32);
                ulonglong2 b2 = *(const ulonglong2*)(bp + 64);
                ulonglong2 b3 = *(const ulonglong2*)(bp + 96);
#pragma unroll
                for (int i = 0; i < 4; i++) {
                    u64 ap = bcast2(f4c(aq[i], dd));
                    acc[i][0] = ffma2(ap, b0.x, acc[i][0]);
                    acc[i][1] = ffma2(ap, b0.y, acc[i][1]);
                    acc[i][2] = ffma2(ap, b1.x, acc[i][2]);
                    acc[i][3] = ffma2(ap, b1.y, acc[i][3]);
                    acc[i][4] = ffma2(ap, b2.x, acc[i][4]);
                    acc[i][5] = ffma2(ap, b2.y, acc[i][5]);
                    acc[i][6] = ffma2(ap, b3.x, acc[i][6]);
                    acc[i][7] = ffma2(ap, b3.y, acc[i][7]);
                }
            }
        }

#pragma unroll
        for (int i = 0; i < 4; i++) {
            float* op = wout + ((size_t)bh * SS + i0 + i * 32 + ty) * SS + j0 + tx * 4;
#pragma unroll
            for (int c = 0; c < 4; c++) {
                float2 p0 = unpk(acc[i][c * 2]), p1 = unpk(acc[i][c * 2 + 1]);
                float4 o4 = make_float4(p0.x * 0.25f, p0.y * 0.25f,
                                        p1.x * 0.25f, p1.y * 0.25f);
                *(float4*)(op + c * 32) = o4;
            }
        }
        __syncthreads();
    }

    // ---- decoupled stats: last sibling block computes row softmax stats ----
    __threadfence();
    __syncthreads();
    const int strip = bh * 16 + blockIdx.y;
    if (tid == 0) s_last = atomicAdd(&g_cnt[strip], 1);
    __syncthreads();
    if (s_last == 3) {
        __threadfence();
        const int wid = tid >> 5, lane = tid & 31;
        const int b = bh >> 4;
        const uchar4* mp = (const uchar4*)(mask + (size_t)b * SS);
        for (int rr = wid; rr < 128; rr += 8) {
            const float4* rp = (const float4*)(wout + ((size_t)bh * SS + i0 + rr) * SS);
            float x[64];
            float mx = -3.0e38f;
#pragma unroll
            for (int v = 0; v < 16; v++) {
                float4 t = rp[lane + v * 32];
                uchar4 m = mp[lane + v * 32];
                x[v * 4 + 0] = m.x ? -1e30f : t.x;
                x[v * 4 + 1] = m.y ? -1e30f : t.y;
                x[v * 4 + 2] = m.z ? -1e30f : t.z;
                x[v * 4 + 3] = m.w ? -1e30f : t.w;
            }
#pragma unroll
            for (int i = 0; i < 64; i++) mx = fmaxf(mx, x[i]);
#pragma unroll
            for (int o = 16; o; o >>= 1) mx = fmaxf(mx, __shfl_xor_sync(0xffffffffu, mx, o));
            float z = 0.f;
#pragma unroll
            for (int i = 0; i < 64; i++) {
                float e = __expf(x[i] - mx);
                x[i] = e;
                z += e;
            }
#pragma unroll
            for (int o = 16; o; o >>= 1) z += __shfl_xor_sync(0xffffffffu, z, o);
            const float cut = 0.01f * z;
            float sk = 0.f;
#pragma unroll
            for (int i = 0; i < 64; i++)
                if (x[i] >= cut) sk += x[i];
#pragma unroll
            for (int o = 16; o; o >>= 1) sk += __shfl_xor_sync(0xffffffffu, sk, o);
            const float inv = sk > 0.f ? 1.f / sk : 0.f;
            if (lane == 0)
                g_stats[(size_t)bh * SS + i0 + rr] = make_float4(mx, cut, inv, 0.f);
        }
        __threadfence();
        __syncthreads();
        if (tid == 0) g_cnt[strip] = 0;   // self-reset for next graph replay
    }
}

// ---------------------------------------------------------------------------
// PV GEMM with fused softmax transform + weights write.
// Reads RAW scores, applies mask/exp/prune/renorm per tile using g_stats,
// writes final weights to wout, and accumulates out = W @ V.
// Tile 128x64, k-chunk 32, 4x16 micro. 128 threads, 4 CTAs/SM.
// ---------------------------------------------------------------------------
#define WPAD 36
#define PV_STAGE (128 * WPAD + 32 * 64)     // 6656 floats per stage
#define PV_SMEM ((2 * PV_STAGE + 384) * 4)  // + mx/cut/inv[128]

__global__ __launch_bounds__(128, 4) void pv_kernel(
    float* __restrict__ wts, float* __restrict__ outp,
    const unsigned char* __restrict__ mask)
{
    extern __shared__ float psm[];
    float* s_mx  = psm + 2 * PV_STAGE;
    float* s_cut = s_mx + 128;
    float* s_inv = s_cut + 128;
    const int tid = threadIdx.x;
    const int tx = tid & 3;            // col base tx*4, chunks +0,+16,+32,+48
    const int ty = tid >> 2;           // 0..31; rows i*32+ty
    const int bh = blockIdx.y;
    const int b = bh >> 4, h = bh & 15;
    const int i0 = blockIdx.x * 128;
    float* Wp = wts + ((size_t)bh * SS + i0) * SS;
    const float* Vp = g_v + (size_t)bh * SS * HD;
    const unsigned char* maskb = mask + (size_t)b * SS;

    // load row stats (written by score kernel)
    {
        float4 s = g_stats[(size_t)bh * SS + i0 + tid];
        s_mx[tid] = s.x; s_cut[tid] = s.y; s_inv[tid] = s.z;
    }

    auto prefetch = [&](int kc, int buf) {
        float* Wt = psm + buf * PV_STAGE;
        float* Vt = Wt + 128 * WPAD;
#pragma unroll
        for (int e = 0; e < 8; e++) {
            int f = e * 128 + tid;
            int r = f >> 3, c4 = f & 7;
            cpa16(&Wt[r * WPAD + c4 * 4], Wp + (size_t)r * SS + kc + c4 * 4);
        }
#pragma unroll
        for (int e = 0; e < 4; e++) {
            int f = e * 128 + tid;
            int j = f >> 4, c4 = f & 15;
            cpa16(&Vt[j * 64 + c4 * 4], Vp + (size_t)(kc + j) * HD + c4 * 4);
        }
        CPA_COMMIT;
    };

    u64 acc[4][8];
#pragma unroll
    for (int i = 0; i < 4; i++)
#pragma unroll
        for (int j = 0; j < 8; j++) acc[i][j] = 0ull;

    prefetch(0, 0);

    for (int it = 0; it < 64; it++) {
        const int kc = it * 32;
        if (it < 63) { prefetch((it + 1) * 32, (it + 1) & 1); CPA_WAIT1; }
        else         { CPA_WAIT0; }
        __syncthreads();
        float* Wt = psm + (it & 1) * PV_STAGE;
        const float* Vt = Wt + 128 * WPAD;

        // ---- softmax transform on the raw score tile + final weights write ----
#pragma unroll
        for (int e = 0; e < 8; e++) {
            int f = e * 128 + tid;
            int r = f >> 3, c4 = f & 7;
            float4 t = *(const float4*)&Wt[r * WPAD + c4 * 4];
            uchar4 m = *(const uchar4*)(maskb + kc + c4 * 4);
            float mx = s_mx[r], cut = s_cut[r], inv = s_inv[r];
            float x0 = m.x ? -1e30f : t.x;
            float x1 = m.y ? -1e30f : t.y;
            float x2 = m.z ? -1e30f : t.z;
            float x3 = m.w ? -1e30f : t.w;
            float e0 = __expf(x0 - mx);
            float e1 = __expf(x1 - mx);
            float e2 = __expf(x2 - mx);
            float e3 = __expf(x3 - mx);
            float4 w;
            w.x = e0 >= cut ? e0 * inv : 0.f;
            w.y = e1 >= cut ? e1 * inv : 0.f;
            w.z = e2 >= cut ? e2 * inv : 0.f;
            w.w = e3 >= cut ? e3 * inv : 0.f;
            *(float4*)&Wt[r * WPAD + c4 * 4] = w;
            *(float4*)(Wp + (size_t)r * SS + kc + c4 * 4) = w;
        }
        __syncthreads();

#pragma unroll
        for (int k4 = 0; k4 < 8; k4++) {
            float4 aw[4];
#pragma unroll
            for (int i = 0; i < 4; i++)
                aw[i] = *(const float4*)&Wt[(i * 32 + ty) * WPAD + k4 * 4];
#pragma unroll
            for (int dd = 0; dd < 4; dd++) {
                const float* bp = &Vt[(k4 * 4 + dd) * 64 + tx * 4];
                ulonglong2 b0 = *(const ulonglong2*)bp;
                ulonglong2 b1 = *(const ulonglong2*)(bp + 16);
                ulonglong2 b2 = *(const ulonglong2*)(bp + 32);
                ulonglong2 b3 = *(const ulonglong2*)(bp + 48);
#pragma unroll
                for (int i = 0; i < 4; i++) {
                    u64 ap = bcast2(f4c(aw[i], dd));
                    acc[i][0] = ffma2(ap, b0.x, acc[i][0]);
                    acc[i][1] = ffma2(ap, b0.y, acc[i][1]);
                    acc[i][2] = ffma2(ap, b1.x, acc[i][2]);
                    acc[i][3] = ffma2(ap, b1.y, acc[i][3]);
                    acc[i][4] = ffma2(ap, b2.x, acc[i][4]);
                    acc[i][5] = ffma2(ap, b2.y, acc[i][5]);
                    acc[i][6] = ffma2(ap, b3.x, acc[i][6]);
                    acc[i][7] = ffma2(ap, b3.y, acc[i][7]);
                }
            }
        }
        __syncthreads();
    }

#pragma unroll
    for (int i = 0; i < 4; i++) {
        int s = i0 + i * 32 + ty;
        float* op = outp + ((size_t)b * SS + s) * HH + h * HD + tx * 4;
#pragma unroll
        for (int c = 0; c < 4; c++) {
            float2 p0 = unpk(acc[i][c * 2]), p1 = unpk(acc[i][c * 2 + 1]);
            float4 o4 = make_float4(p0.x, p0.y, p1.x, p1.y);
            *(float4*)(op + c * 16) = o4;
        }
    }
}

// ---------------------------------------------------------------------------
extern "C" void kernel_launch(void* const* d_in, const int* in_sizes, int n_in,
                              void* d_out, int out_size)
{
    const float* query = (const float*)d_in[0];
    const float* key   = (const float*)d_in[1];
    const float* value = (const float*)d_in[2];
    const unsigned char* mask = (const unsigned char*)d_in[3];
    const float* Wq = (const float*)d_in[4];
    const float* bq = (const float*)d_in[5];
    const float* Wk = (const float*)d_in[6];
    const float* bk = (const float*)d_in[7];
    const float* Wv = (const float*)d_in[8];
    const float* bv = (const float*)d_in[9];

    float* outp = (float*)d_out;                        // [B,S,H]
    float* wts  = outp + (size_t)BB * SS * HH;          // [B,h,S,S]

    float *gq, *gk, *gv, *gkt, *gwt;
    cudaGetSymbolAddress((void**)&gq, g_q);
    cudaGetSymbolAddress((void**)&gk, g_k);
    cudaGetSymbolAddress((void**)&gv, g_v);
    cudaGetSymbolAddress((void**)&gkt, g_kt);
    cudaGetSymbolAddress((void**)&gwt, g_wt);

    cudaFuncSetAttribute(proj_kernel, cudaFuncAttributeMaxDynamicSharedMemorySize,
                         PROJ_SMEM);
    cudaFuncSetAttribute(score_kernel, cudaFuncAttributeMaxDynamicSharedMemorySize,
                         SCORE_SMEM);
    cudaFuncSetAttribute(pv_kernel, cudaFuncAttributeMaxDynamicSharedMemorySize,
                         PV_SMEM);

    dim3 tb(32, 8);

    transpose_w3<<<dim3(32, 32, 3), tb>>>(Wq, Wk, Wv, gwt);

    dim3 pgrid(HH / 128, NROWS / 64, 3);
    proj_kernel<<<pgrid, 128, PROJ_SMEM>>>(query, key, value, gwt, bq, bk, bv, gq, gk, gv);

    dim3 tkgrid(SS / 32, HD / 32, BH);
    transpose_k<<<tkgrid, tb>>>(gk, gkt);

    dim3 sgrid(SS / 128 / 4, SS / 128, BH);
    score_kernel<<<sgrid, 256, SCORE_SMEM>>>(wts, mask);

    dim3 vgrid(SS / 128, BH);
    pv_kernel<<<vgrid, 128, PV_SMEM>>>(wts, outp, mask);
}

// round 15
// speedup vs baseline: 1.2169x; 1.0123x over previous
#include <cuda_runtime.h>
#include <math.h>
#include <stdint.h>

#define BB 2
#define SS 2048
#define HH 1024
#define NH 16
#define HD 64
#define BH 32
#define NROWS 4096

// scratch (static __device__ arrays; no runtime allocation)
__device__ float g_q[(size_t)BH * SS * HD];
__device__ float g_k[(size_t)BH * SS * HD];
__device__ float g_v[(size_t)BH * SS * HD];
__device__ float g_kt[(size_t)BH * HD * SS];      // K transposed: [bh][d][s]
__device__ float g_wt[3 * (size_t)HH * HH];       // Wq,Wk,Wv transposed: [k][n]

typedef unsigned long long u64;

// ---- packed fp32x2 helpers (sm_103a FFMA2) ----
__device__ __forceinline__ u64 bcast2(float x) {
    u64 d; unsigned int u = __float_as_uint(x);
    asm("mov.b64 %0, {%1,%2};" : "=l"(d) : "r"(u), "r"(u));
    return d;
}
__device__ __forceinline__ u64 ffma2(u64 a, u64 b, u64 c) {
    u64 d;
    asm("fma.rn.f32x2 %0, %1, %2, %3;" : "=l"(d) : "l"(a), "l"(b), "l"(c));
    return d;
}
__device__ __forceinline__ float2 unpk(u64 v) {
    unsigned int lo, hi;
    asm("mov.b64 {%0,%1}, %2;" : "=r"(lo), "=r"(hi) : "l"(v));
    return make_float2(__uint_as_float(lo), __uint_as_float(hi));
}
__device__ __forceinline__ float f4c(const float4& v, int i) {
    return i == 0 ? v.x : i == 1 ? v.y : i == 2 ? v.z : v.w;
}

// ---- cp.async helpers ----
__device__ __forceinline__ void cpa16(void* s, const void* g) {
    unsigned int sa = (unsigned int)__cvta_generic_to_shared(s);
    asm volatile("cp.async.ca.shared.global [%0], [%1], 16;" :: "r"(sa), "l"(g));
}
#define CPA_COMMIT  asm volatile("cp.async.commit_group;")
#define CPA_WAIT1   asm volatile("cp.async.wait_group 1;")
#define CPA_WAIT0   asm volatile("cp.async.wait_group 0;")

// ---------------------------------------------------------------------------
// Transpose all three W matrices: g_wt[z][k][n] = W_z[n][k]
// ---------------------------------------------------------------------------
__global__ __launch_bounds__(256) void transpose_w3(
    const float* __restrict__ Wq, const float* __restrict__ Wk,
    const float* __restrict__ Wv, float* __restrict__ outp)
{
    __shared__ float t[32][33];
    const int z = blockIdx.z;
    const float* in = z == 0 ? Wq : z == 1 ? Wk : Wv;
    float* op = outp + (size_t)z * HH * HH;
    const int x0 = blockIdx.x * 32, y0 = blockIdx.y * 32;
    const int x = threadIdx.x, y = threadIdx.y;   // 32 x 8
    for (int i = y; i < 32; i += 8) t[i][x] = in[(size_t)(y0 + i) * HH + x0 + x];
    __syncthreads();
    for (int i = y; i < 32; i += 8) op[(size_t)(x0 + i) * HH + y0 + x] = t[x][i];
}

// ---------------------------------------------------------------------------
// Transpose K: [bh][s][d] -> [bh][d][s]
// ---------------------------------------------------------------------------
__global__ __launch_bounds__(256) void transpose_k(
    const float* __restrict__ in, float* __restrict__ outp)
{
    __shared__ float t[32][33];
    const int bh = blockIdx.z;
    const int s0 = blockIdx.x * 32;
    const int d0 = blockIdx.y * 32;
    const int x = threadIdx.x, y = threadIdx.y;   // 32 x 8
    const float* ip = in + ((size_t)bh * SS + s0) * HD + d0;
    for (int i = y; i < 32; i += 8) t[i][x] = ip[(size_t)i * HD + x];
    __syncthreads();
    float* op = outp + ((size_t)bh * HD + d0) * SS + s0;
    for (int i = y; i < 32; i += 8) op[(size_t)i * SS + x] = t[x][i];
}

// ---------------------------------------------------------------------------
// Fused QKV projection GEMM (grid.z selects q/k/v): out = X @ W^T + b,
// scattered to [bh][s][d]. For z==0 (q) the result is pre-scaled by 0.25
// (exact pow-2 scaling; commutes bitwise with the score accumulation).
// Tile 64(M)x128(N), BK=32, 4x16 FFMA2 micro-tile. 128 threads, 4 CTAs/SM.
// ---------------------------------------------------------------------------
#define APAD 36
#define PROJ_STAGE (64 * APAD + 32 * 128)    // 6400 floats per stage
#define PROJ_SMEM (2 * PROJ_STAGE * 4)       // 51.2 KB

__global__ __launch_bounds__(128, 4) void proj_kernel(
    const float* __restrict__ Xq, const float* __restrict__ Xk,
    const float* __restrict__ Xv, const float* __restrict__ Wt3,
    const float* __restrict__ bq, const float* __restrict__ bk,
    const float* __restrict__ bv,
    float* __restrict__ oq, float* __restrict__ ok, float* __restrict__ ov)
{
    extern __shared__ float sm[];
    const int z = blockIdx.z;
    const float* X    = z == 0 ? Xq : z == 1 ? Xk : Xv;
    const float* Wt   = Wt3 + (size_t)z * HH * HH;
    const float* bias = z == 0 ? bq : z == 1 ? bk : bv;
    float* outp       = z == 0 ? oq : z == 1 ? ok : ov;
    const float qs    = z == 0 ? 0.25f : 1.0f;   // fold score scale into q

    const int tid = threadIdx.x;
    const int tx = tid & 7;            // col base tx*4, chunks +0,+32,+64,+96
    const int ty = tid >> 3;           // 0..15; rows i*16+ty
    const int i0 = blockIdx.y * 64;
    const int j0 = blockIdx.x * 128;

    auto prefetch = [&](int k0, int buf) {
        float* As = sm + buf * PROJ_STAGE;
        float* Bs = As + 64 * APAD;
#pragma unroll
        for (int e = 0; e < 4; e++) {
            int f = e * 128 + tid;
            int r = f >> 3, c4 = f & 7;
            cpa16(&As[r * APAD + c4 * 4], X + (size_t)(i0 + r) * HH + k0 + c4 * 4);
        }
#pragma unroll
        for (int e = 0; e < 8; e++) {
            int f = e * 128 + tid;
            int k = f >> 5, c = f & 31;
            cpa16(&Bs[k * 128 + c * 4], Wt + (size_t)(k0 + k) * HH + j0 + c * 4);
        }
        CPA_COMMIT;
    };

    u64 acc[4][8];
#pragma unroll
    for (int i = 0; i < 4; i++)
#pragma unroll
        for (int j = 0; j < 8; j++) acc[i][j] = 0ull;

    prefetch(0, 0);

    for (int it = 0; it < 32; it++) {
        if (it < 31) { prefetch((it + 1) * 32, (it + 1) & 1); CPA_WAIT1; }
        else         { CPA_WAIT0; }
        __syncthreads();
        const float* As = sm + (it & 1) * PROJ_STAGE;
        const float* Bs = As + 64 * APAD;
#pragma unroll
        for (int k4 = 0; k4 < 8; k4++) {
            float4 aq[4];
#pragma unroll
            for (int i = 0; i < 4; i++)
                aq[i] = *(const float4*)&As[(i * 16 + ty) * APAD + k4 * 4];
#pragma unroll
            for (int dd = 0; dd < 4; dd++) {
                const float* bp = &Bs[(k4 * 4 + dd) * 128 + tx * 4];
                ulonglong2 b0 = *(const ulonglong2*)bp;
                ulonglong2 b1 = *(const ulonglong2*)(bp + 32);
                ulonglong2 b2 = *(const ulonglong2*)(bp + 64);
                ulonglong2 b3 = *(const ulonglong2*)(bp + 96);
#pragma unroll
                for (int i = 0; i < 4; i++) {
                    u64 ap = bcast2(f4c(aq[i], dd));
                    acc[i][0] = ffma2(ap, b0.x, acc[i][0]);
                    acc[i][1] = ffma2(ap, b0.y, acc[i][1]);
                    acc[i][2] = ffma2(ap, b1.x, acc[i][2]);
                    acc[i][3] = ffma2(ap, b1.y, acc[i][3]);
                    acc[i][4] = ffma2(ap, b2.x, acc[i][4]);
                    acc[i][5] = ffma2(ap, b2.y, acc[i][5]);
                    acc[i][6] = ffma2(ap, b3.x, acc[i][6]);
                    acc[i][7] = ffma2(ap, b3.y, acc[i][7]);
                }
            }
        }
        __syncthreads();
    }

#pragma unroll
    for (int c = 0; c < 4; c++) {
        const int col = j0 + tx * 4 + c * 32;
        const int h = col >> 6, d = col & 63;
        float4 bb = *(const float4*)(bias + col);
#pragma unroll
        for (int i = 0; i < 4; i++) {
            int r = i0 + i * 16 + ty;
            int b = r >> 11, s = r & 2047;
            float2 p0 = unpk(acc[i][c * 2]), p1 = unpk(acc[i][c * 2 + 1]);
            float4 o4 = make_float4((p0.x + bb.x) * qs, (p0.y + bb.y) * qs,
                                    (p1.x + bb.z) * qs, (p1.y + bb.w) * qs);
            *(float4*)(outp + (((size_t)(b * NH + h)) * SS + s) * HD + d) = o4;
        }
    }
}

// ---------------------------------------------------------------------------
// Score GEMM: wout[bh][i][j] = sum_d q'[i,d]*k[j,d]  (q' pre-scaled by 0.25).
// Block = 128 i-rows x (8 consecutive 128-wide j-tiles). Q loaded once,
// K^T double-buffered. 4x16 micro-tile. 2 CTAs/SM (128-reg cap).
// ---------------------------------------------------------------------------
#define QPAD 68
#define KSTAGE (64 * 128)
#define SCORE_SMEM ((128 * QPAD + 2 * KSTAGE) * 4)
#define JGRP 8

__global__ __launch_bounds__(256, 2) void score_kernel(float* __restrict__ wout)
{
    extern __shared__ float sm[];
    float* Qs = sm;                       // [128][QPAD]
    float* Kbuf = sm + 128 * QPAD;        // 2 x [64][128]
    const int tid = threadIdx.x;
    const int tx = tid & 7;               // col base tx*4, chunks +0,+32,+64,+96
    const int ty = tid >> 3;              // 0..31; rows i*32+ty
    const int bh = blockIdx.z;
    const int i0 = blockIdx.y * 128;
    const int jb0 = blockIdx.x * JGRP;

    const float* Qp = g_q + ((size_t)bh * SS + i0) * HD;
    const float* Ktp = g_kt + (size_t)bh * HD * SS;

#pragma unroll
    for (int e = 0; e < 8; e++) {
        int f = e * 256 + tid;
        int r = f >> 4, c4 = f & 15;
        cpa16(&Qs[r * QPAD + c4 * 4], Qp + (size_t)r * HD + c4 * 4);
    }
    CPA_COMMIT;

    auto prefetchK = [&](int j0, int buf) {
        float* Ks = Kbuf + buf * KSTAGE;
#pragma unroll
        for (int e = 0; e < 8; e++) {
            int f = e * 256 + tid;
            int d = f >> 5, c = f & 31;
            cpa16(&Ks[d * 128 + c * 4], Ktp + (size_t)d * SS + j0 + c * 4);
        }
        CPA_COMMIT;
    };
    prefetchK(jb0 * 128, 0);

    for (int jt = 0; jt < JGRP; jt++) {
        const int j0 = (jb0 + jt) * 128;
        if (jt < JGRP - 1) { prefetchK(j0 + 128, (jt + 1) & 1); CPA_WAIT1; }
        else               { CPA_WAIT0; }
        __syncthreads();
        const float* Ks = Kbuf + (jt & 1) * KSTAGE;

        u64 acc[4][8];
#pragma unroll
        for (int i = 0; i < 4; i++)
#pragma unroll
            for (int j = 0; j < 8; j++) acc[i][j] = 0ull;

#pragma unroll 4
        for (int d4 = 0; d4 < 16; d4++) {
            float4 aq[4];
#pragma unroll
            for (int i = 0; i < 4; i++)
                aq[i] = *(const float4*)&Qs[(i * 32 + ty) * QPAD + d4 * 4];
#pragma unroll
            for (int dd = 0; dd < 4; dd++) {
                const float* bp = &Ks[(d4 * 4 + dd) * 128 + tx * 4];
                ulonglong2 b0 = *(const ulonglong2*)bp;
                ulonglong2 b1 = *(const ulonglong2*)(bp + 32);
                ulonglong2 b2 = *(const ulonglong2*)(bp + 64);
                ulonglong2 b3 = *(const ulonglong2*)(bp + 96);
#pragma unroll
                for (int i = 0; i < 4; i++) {
                    u64 ap = bcast2(f4c(aq[i], dd));
                    acc[i][0] = ffma2(ap, b0.x, acc[i][0]);
                    acc[i][1] = ffma2(ap, b0.y, acc[i][1]);
                    acc[i][2] = ffma2(ap, b1.x, acc[i][2]);
                    acc[i][3] = ffma2(ap, b1.y, acc[i][3]);
                    acc[i][4] = ffma2(ap, b2.x, acc[i][4]);
                    acc[i][5] = ffma2(ap, b2.y, acc[i][5]);
                    acc[i][6] = ffma2(ap, b3.x, acc[i][6]);
                    acc[i][7] = ffma2(ap, b3.y, acc[i][7]);
                }
            }
        }

#pragma unroll
        for (int i = 0; i < 4; i++) {
            float* op = wout + ((size_t)bh * SS + i0 + i * 32 + ty) * SS + j0 + tx * 4;
#pragma unroll
            for (int c = 0; c < 4; c++) {
                float2 p0 = unpk(acc[i][c * 2]), p1 = unpk(acc[i][c * 2 + 1]);
                float4 o4 = make_float4(p0.x, p0.y, p1.x, p1.y);
                *(float4*)(op + c * 32) = o4;
            }
        }
        __syncthreads();
    }
}

// ---------------------------------------------------------------------------
// Row softmax + threshold prune + L1 renorm, in place (exact fp32 path).
// One warp per row; 2048 floats in 64 regs/lane.
// ---------------------------------------------------------------------------
__global__ __launch_bounds__(256) void softmax_kernel(
    const unsigned char* __restrict__ mask, float* __restrict__ w)
{
    const int lane = threadIdx.x & 31;
    const size_t row = (size_t)blockIdx.x * 8 + (threadIdx.x >> 5);
    const int b = (int)(row >> 15);
    float4* rp = (float4*)(w + row * SS);
    const uchar4* mp = (const uchar4*)(mask + (size_t)b * SS);

    float x[64];
    float mx = -3.0e38f;
#pragma unroll
    for (int v = 0; v < 16; v++) {
        float4 t = rp[lane + v * 32];
        uchar4 m = mp[lane + v * 32];
        x[v * 4 + 0] = m.x ? -1e30f : t.x;
        x[v * 4 + 1] = m.y ? -1e30f : t.y;
        x[v * 4 + 2] = m.z ? -1e30f : t.z;
        x[v * 4 + 3] = m.w ? -1e30f : t.w;
    }
#pragma unroll
    for (int i = 0; i < 64; i++) mx = fmaxf(mx, x[i]);
#pragma unroll
    for (int o = 16; o; o >>= 1) mx = fmaxf(mx, __shfl_xor_sync(0xffffffffu, mx, o));

    float z = 0.f;
#pragma unroll
    for (int i = 0; i < 64; i++) {
        float e = __expf(x[i] - mx);
        x[i] = e;
        z += e;
    }
#pragma unroll
    for (int o = 16; o; o >>= 1) z += __shfl_xor_sync(0xffffffffu, z, o);

    const float cut = 0.01f * z;
    float sk = 0.f;
#pragma unroll
    for (int i = 0; i < 64; i++)
        if (x[i] >= cut) sk += x[i];
#pragma unroll
    for (int o = 16; o; o >>= 1) sk += __shfl_xor_sync(0xffffffffu, sk, o);
    const float inv = sk > 0.f ? 1.f / sk : 0.f;

#pragma unroll
    for (int v = 0; v < 16; v++) {
        float4 o4;
        o4.x = x[v * 4 + 0] >= cut ? x[v * 4 + 0] * inv : 0.f;
        o4.y = x[v * 4 + 1] >= cut ? x[v * 4 + 1] * inv : 0.f;
        o4.z = x[v * 4 + 2] >= cut ? x[v * 4 + 2] * inv : 0.f;
        o4.w = x[v * 4 + 3] >= cut ? x[v * 4 + 3] * inv : 0.f;
        rp[lane + v * 32] = o4;
    }
}

// ---------------------------------------------------------------------------
// PV GEMM: out[b][s][h*64+d] = sum_j W[bh][i][j] * V[bh][j][d].
// Tile 128x64, k-chunk 32, 4x16 micro. 128 threads, 4 CTAs/SM.
// ---------------------------------------------------------------------------
#define WPAD 36
#define PV_STAGE (128 * WPAD + 32 * 64)     // 6656 floats per stage
#define PV_SMEM (2 * PV_STAGE * 4)          // 53.2 KB

__global__ __launch_bounds__(128, 4) void pv_kernel(
    const float* __restrict__ wts, float* __restrict__ outp)
{
    extern __shared__ float psm[];
    const int tid = threadIdx.x;
    const int tx = tid & 3;            // col base tx*4, chunks +0,+16,+32,+48
    const int ty = tid >> 2;           // 0..31; rows i*32+ty
    const int bh = blockIdx.y;
    const int b = bh >> 4, h = bh & 15;
    const int i0 = blockIdx.x * 128;
    const float* Wp = wts + ((size_t)bh * SS + i0) * SS;
    const float* Vp = g_v + (size_t)bh * SS * HD;

    auto prefetch = [&](int kc, int buf) {
        float* Wt = psm + buf * PV_STAGE;
        float* Vt = Wt + 128 * WPAD;
#pragma unroll
        for (int e = 0; e < 8; e++) {
            int f = e * 128 + tid;
            int r = f >> 3, c4 = f & 7;
            cpa16(&Wt[r * WPAD + c4 * 4], Wp + (size_t)r * SS + kc + c4 * 4);
        }
#pragma unroll
        for (int e = 0; e < 4; e++) {
            int f = e * 128 + tid;
            int j = f >> 4, c4 = f & 15;
            cpa16(&Vt[j * 64 + c4 * 4], Vp + (size_t)(kc + j) * HD + c4 * 4);
        }
        CPA_COMMIT;
    };

    u64 acc[4][8];
#pragma unroll
    for (int i = 0; i < 4; i++)
#pragma unroll
        for (int j = 0; j < 8; j++) acc[i][j] = 0ull;

    prefetch(0, 0);

    for (int it = 0; it < 64; it++) {
        if (it < 63) { prefetch((it + 1) * 32, (it + 1) & 1); CPA_WAIT1; }
        else         { CPA_WAIT0; }
        __syncthreads();
        const float* Wt = psm + (it & 1) * PV_STAGE;
        const float* Vt = Wt + 128 * WPAD;
#pragma unroll
        for (int k4 = 0; k4 < 8; k4++) {
            float4 aw[4];
#pragma unroll
            for (int i = 0; i < 4; i++)
                aw[i] = *(const float4*)&Wt[(i * 32 + ty) * WPAD + k4 * 4];
#pragma unroll
            for (int dd = 0; dd < 4; dd++) {
                const float* bp = &Vt[(k4 * 4 + dd) * 64 + tx * 4];
                ulonglong2 b0 = *(const ulonglong2*)bp;
                ulonglong2 b1 = *(const ulonglong2*)(bp + 16);
                ulonglong2 b2 = *(const ulonglong2*)(bp + 32);
                ulonglong2 b3 = *(const ulonglong2*)(bp + 48);
#pragma unroll
                for (int i = 0; i < 4; i++) {
                    u64 ap = bcast2(f4c(aw[i], dd));
                    acc[i][0] = ffma2(ap, b0.x, acc[i][0]);
                    acc[i][1] = ffma2(ap, b0.y, acc[i][1]);
                    acc[i][2] = ffma2(ap, b1.x, acc[i][2]);
                    acc[i][3] = ffma2(ap, b1.y, acc[i][3]);
                    acc[i][4] = ffma2(ap, b2.x, acc[i][4]);
                    acc[i][5] = ffma2(ap, b2.y, acc[i][5]);
                    acc[i][6] = ffma2(ap, b3.x, acc[i][6]);
                    acc[i][7] = ffma2(ap, b3.y, acc[i][7]);
                }
            }
        }
        __syncthreads();
    }

#pragma unroll
    for (int i = 0; i < 4; i++) {
        int s = i0 + i * 32 + ty;
        float* op = outp + ((size_t)b * SS + s) * HH + h * HD + tx * 4;
#pragma unroll
        for (int c = 0; c < 4; c++) {
            float2 p0 = unpk(acc[i][c * 2]), p1 = unpk(acc[i][c * 2 + 1]);
            float4 o4 = make_float4(p0.x, p0.y, p1.x, p1.y);
            *(float4*)(op + c * 16) = o4;
        }
    }
}

// ---------------------------------------------------------------------------
extern "C" void kernel_launch(void* const* d_in, const int* in_sizes, int n_in,
                              void* d_out, int out_size)
{
    const float* query = (const float*)d_in[0];
    const float* key   = (const float*)d_in[1];
    const float* value = (const float*)d_in[2];
    const unsigned char* mask = (const unsigned char*)d_in[3];
    const float* Wq = (const float*)d_in[4];
    const float* bq = (const float*)d_in[5];
    const float* Wk = (const float*)d_in[6];
    const float* bk = (const float*)d_in[7];
    const float* Wv = (const float*)d_in[8];
    const float* bv = (const float*)d_in[9];

    float* outp = (float*)d_out;                        // [B,S,H]
    float* wts  = outp + (size_t)BB * SS * HH;          // [B,h,S,S]

    float *gq, *gk, *gv, *gkt, *gwt;
    cudaGetSymbolAddress((void**)&gq, g_q);
    cudaGetSymbolAddress((void**)&gk, g_k);
    cudaGetSymbolAddress((void**)&gv, g_v);
    cudaGetSymbolAddress((void**)&gkt, g_kt);
    cudaGetSymbolAddress((void**)&gwt, g_wt);

    cudaFuncSetAttribute(proj_kernel, cudaFuncAttributeMaxDynamicSharedMemorySize,
                         PROJ_SMEM);
    cudaFuncSetAttribute(score_kernel, cudaFuncAttributeMaxDynamicSharedMemorySize,
                         SCORE_SMEM);
    cudaFuncSetAttribute(pv_kernel, cudaFuncAttributeMaxDynamicSharedMemorySize,
                         PV_SMEM);

    dim3 tb(32, 8);

    transpose_w3<<<dim3(32, 32, 3), tb>>>(Wq, Wk, Wv, gwt);

    dim3 pgrid(HH / 128, NROWS / 64, 3);
    proj_kernel<<<pgrid, 128, PROJ_SMEM>>>(query, key, value, gwt, bq, bk, bv, gq, gk, gv);

    dim3 tkgrid(SS / 32, HD / 32, BH);
    transpose_k<<<tkgrid, tb>>>(gk, gkt);

    dim3 sgrid(SS / 128 / JGRP, SS / 128, BH);
    score_kernel<<<sgrid, 256, SCORE_SMEM>>>(wts);

    softmax_kernel<<<(BH * SS) / 8, 256>>>(mask, wts);

    dim3 vgrid(SS / 128, BH);
    pv_kernel<<<vgrid, 128, PV_SMEM>>>(wts, outp);
}

// round 16
// speedup vs baseline: 1.2703x; 1.0439x over previous
#include <cuda_runtime.h>
#include <math.h>
#include <stdint.h>

#define BB 2
#define SS 2048
#define HH 1024
#define NH 16
#define HD 64
#define BH 32
#define NROWS 4096

// scratch (static __device__ arrays; no runtime allocation)
__device__ float g_q[(size_t)BH * SS * HD];
__device__ float g_k[(size_t)BH * SS * HD];
__device__ float g_v[(size_t)BH * SS * HD];
__device__ float g_kt[(size_t)BH * HD * SS];      // K transposed: [bh][d][s]
__device__ float g_wt[3 * (size_t)HH * HH];       // Wq,Wk,Wv transposed: [k][n]

typedef unsigned long long u64;

// ---- packed fp32x2 helpers (sm_103a FFMA2) ----
__device__ __forceinline__ u64 bcast2(float x) {
    u64 d; unsigned int u = __float_as_uint(x);
    asm("mov.b64 %0, {%1,%2};" : "=l"(d) : "r"(u), "r"(u));
    return d;
}
__device__ __forceinline__ u64 ffma2(u64 a, u64 b, u64 c) {
    u64 d;
    asm("fma.rn.f32x2 %0, %1, %2, %3;" : "=l"(d) : "l"(a), "l"(b), "l"(c));
    return d;
}
__device__ __forceinline__ float2 unpk(u64 v) {
    unsigned int lo, hi;
    asm("mov.b64 {%0,%1}, %2;" : "=r"(lo), "=r"(hi) : "l"(v));
    return make_float2(__uint_as_float(lo), __uint_as_float(hi));
}
__device__ __forceinline__ float f4c(const float4& v, int i) {
    return i == 0 ? v.x : i == 1 ? v.y : i == 2 ? v.z : v.w;
}

// ---- cp.async helpers ----
__device__ __forceinline__ void cpa16(void* s, const void* g) {
    unsigned int sa = (unsigned int)__cvta_generic_to_shared(s);
    asm volatile("cp.async.ca.shared.global [%0], [%1], 16;" :: "r"(sa), "l"(g));
}
#define CPA_COMMIT  asm volatile("cp.async.commit_group;")
#define CPA_WAIT1   asm volatile("cp.async.wait_group 1;")
#define CPA_WAIT0   asm volatile("cp.async.wait_group 0;")

// ---------------------------------------------------------------------------
// Transpose all three W matrices: g_wt[z][k][n] = W_z[n][k]
// ---------------------------------------------------------------------------
__global__ __launch_bounds__(256) void transpose_w3(
    const float* __restrict__ Wq, const float* __restrict__ Wk,
    const float* __restrict__ Wv, float* __restrict__ outp)
{
    __shared__ float t[32][33];
    const int z = blockIdx.z;
    const float* in = z == 0 ? Wq : z == 1 ? Wk : Wv;
    float* op = outp + (size_t)z * HH * HH;
    const int x0 = blockIdx.x * 32, y0 = blockIdx.y * 32;
    const int x = threadIdx.x, y = threadIdx.y;   // 32 x 8
    for (int i = y; i < 32; i += 8) t[i][x] = in[(size_t)(y0 + i) * HH + x0 + x];
    __syncthreads();
    for (int i = y; i < 32; i += 8) op[(size_t)(x0 + i) * HH + y0 + x] = t[x][i];
}

// ---------------------------------------------------------------------------
// Transpose K: [bh][s][d] -> [bh][d][s]
// ---------------------------------------------------------------------------
__global__ __launch_bounds__(256) void transpose_k(
    const float* __restrict__ in, float* __restrict__ outp)
{
    __shared__ float t[32][33];
    const int bh = blockIdx.z;
    const int s0 = blockIdx.x * 32;
    const int d0 = blockIdx.y * 32;
    const int x = threadIdx.x, y = threadIdx.y;   // 32 x 8
    const float* ip = in + ((size_t)bh * SS + s0) * HD + d0;
    for (int i = y; i < 32; i += 8) t[i][x] = ip[(size_t)i * HD + x];
    __syncthreads();
    float* op = outp + ((size_t)bh * HD + d0) * SS + s0;
    for (int i = y; i < 32; i += 8) op[(size_t)i * SS + x] = t[x][i];
}

// ---------------------------------------------------------------------------
// Fused QKV projection GEMM (grid.z selects q/k/v): out = X @ W^T + b,
// scattered to [bh][s][d]. Tile 64(M)x128(N), BK=32, 4x16 FFMA2 micro-tile
// (rows i*16+ty, cols tx*4+{0,32,64,96}). 128 threads, 4 CTAs/SM.
// ---------------------------------------------------------------------------
#define APAD 36
#define PROJ_STAGE (64 * APAD + 32 * 128)    // 6400 floats per stage
#define PROJ_SMEM (2 * PROJ_STAGE * 4)       // 51.2 KB

__global__ __launch_bounds__(128, 4) void proj_kernel(
    const float* __restrict__ Xq, const float* __restrict__ Xk,
    const float* __restrict__ Xv, const float* __restrict__ Wt3,
    const float* __restrict__ bq, const float* __restrict__ bk,
    const float* __restrict__ bv,
    float* __restrict__ oq, float* __restrict__ ok, float* __restrict__ ov)
{
    extern __shared__ float sm[];
    const int z = blockIdx.z;
    const float* X    = z == 0 ? Xq : z == 1 ? Xk : Xv;
    const float* Wt   = Wt3 + (size_t)z * HH * HH;
    const float* bias = z == 0 ? bq : z == 1 ? bk : bv;
    float* outp       = z == 0 ? oq : z == 1 ? ok : ov;

    const int tid = threadIdx.x;
    const int tx = tid & 7;            // col base tx*4, chunks +0,+32,+64,+96
    const int ty = tid >> 3;           // 0..15; rows i*16+ty
    const int i0 = blockIdx.y * 64;
    const int j0 = blockIdx.x * 128;

    auto prefetch = [&](int k0, int buf) {
        float* As = sm + buf * PROJ_STAGE;
        float* Bs = As + 64 * APAD;
#pragma unroll
        for (int e = 0; e < 4; e++) {
            int f = e * 128 + tid;
            int r = f >> 3, c4 = f & 7;
            cpa16(&As[r * APAD + c4 * 4], X + (size_t)(i0 + r) * HH + k0 + c4 * 4);
        }
#pragma unroll
        for (int e = 0; e < 8; e++) {
            int f = e * 128 + tid;
            int k = f >> 5, c = f & 31;
            cpa16(&Bs[k * 128 + c * 4], Wt + (size_t)(k0 + k) * HH + j0 + c * 4);
        }
        CPA_COMMIT;
    };

    u64 acc[4][8];
#pragma unroll
    for (int i = 0; i < 4; i++)
#pragma unroll
        for (int j = 0; j < 8; j++) acc[i][j] = 0ull;

    prefetch(0, 0);

    for (int it = 0; it < 32; it++) {
        if (it < 31) { prefetch((it + 1) * 32, (it + 1) & 1); CPA_WAIT1; }
        else         { CPA_WAIT0; }
        __syncthreads();
        const float* As = sm + (it & 1) * PROJ_STAGE;
        const float* Bs = As + 64 * APAD;
#pragma unroll
        for (int k4 = 0; k4 < 8; k4++) {
            float4 aq[4];
#pragma unroll
            for (int i = 0; i < 4; i++)
                aq[i] = *(const float4*)&As[(i * 16 + ty) * APAD + k4 * 4];
#pragma unroll
            for (int dd = 0; dd < 4; dd++) {
                const float* bp = &Bs[(k4 * 4 + dd) * 128 + tx * 4];
                ulonglong2 b0 = *(const ulonglong2*)bp;
                ulonglong2 b1 = *(const ulonglong2*)(bp + 32);
                ulonglong2 b2 = *(const ulonglong2*)(bp + 64);
                ulonglong2 b3 = *(const ulonglong2*)(bp + 96);
#pragma unroll
                for (int i = 0; i < 4; i++) {
                    u64 ap = bcast2(f4c(aq[i], dd));
                    acc[i][0] = ffma2(ap, b0.x, acc[i][0]);
                    acc[i][1] = ffma2(ap, b0.y, acc[i][1]);
                    acc[i][2] = ffma2(ap, b1.x, acc[i][2]);
                    acc[i][3] = ffma2(ap, b1.y, acc[i][3]);
                    acc[i][4] = ffma2(ap, b2.x, acc[i][4]);
                    acc[i][5] = ffma2(ap, b2.y, acc[i][5]);
                    acc[i][6] = ffma2(ap, b3.x, acc[i][6]);
                    acc[i][7] = ffma2(ap, b3.y, acc[i][7]);
                }
            }
        }
        __syncthreads();
    }

#pragma unroll
    for (int c = 0; c < 4; c++) {
        const int col = j0 + tx * 4 + c * 32;
        const int h = col >> 6, d = col & 63;
        float4 bb = *(const float4*)(bias + col);
#pragma unroll
        for (int i = 0; i < 4; i++) {
            int r = i0 + i * 16 + ty;
            int b = r >> 11, s = r & 2047;
            float2 p0 = unpk(acc[i][c * 2]), p1 = unpk(acc[i][c * 2 + 1]);
            float4 o4 = make_float4(p0.x + bb.x, p0.y + bb.y, p1.x + bb.z, p1.y + bb.w);
            *(float4*)(outp + (((size_t)(b * NH + h)) * SS + s) * HD + d) = o4;
        }
    }
}

// ---------------------------------------------------------------------------
// Score GEMM: wout[bh][i][j] = 0.25 * sum_d q[i,d]*k[j,d].
// Block = 128 i-rows x (4 consecutive 128-wide j-tiles). 4x16 micro-tile
// (rows i*32+ty, cols tx*4+{0,32,64,96}). 2 CTAs/SM (128-reg cap).
// ---------------------------------------------------------------------------
#define QPAD 68
#define KSTAGE (64 * 128)
#define SCORE_SMEM ((128 * QPAD + 2 * KSTAGE) * 4)

__global__ __launch_bounds__(256, 2) void score_kernel(float* __restrict__ wout)
{
    extern __shared__ float sm[];
    float* Qs = sm;                       // [128][QPAD]
    float* Kbuf = sm + 128 * QPAD;        // 2 x [64][128]
    const int tid = threadIdx.x;
    const int tx = tid & 7;               // col base tx*4, chunks +0,+32,+64,+96
    const int ty = tid >> 3;              // 0..31; rows i*32+ty
    const int bh = blockIdx.z;
    const int i0 = blockIdx.y * 128;
    const int jb0 = blockIdx.x * 4;

    const float* Qp = g_q + ((size_t)bh * SS + i0) * HD;
    const float* Ktp = g_kt + (size_t)bh * HD * SS;

#pragma unroll
    for (int e = 0; e < 8; e++) {
        int f = e * 256 + tid;
        int r = f >> 4, c4 = f & 15;
        cpa16(&Qs[r * QPAD + c4 * 4], Qp + (size_t)r * HD + c4 * 4);
    }
    CPA_COMMIT;

    auto prefetchK = [&](int j0, int buf) {
        float* Ks = Kbuf + buf * KSTAGE;
#pragma unroll
        for (int e = 0; e < 8; e++) {
            int f = e * 256 + tid;
            int d = f >> 5, c = f & 31;
            cpa16(&Ks[d * 128 + c * 4], Ktp + (size_t)d * SS + j0 + c * 4);
        }
        CPA_COMMIT;
    };
    prefetchK(jb0 * 128, 0);

    for (int jt = 0; jt < 4; jt++) {
        const int j0 = (jb0 + jt) * 128;
        if (jt < 3) { prefetchK(j0 + 128, (jt + 1) & 1); CPA_WAIT1; }
        else        { CPA_WAIT0; }
        __syncthreads();
        const float* Ks = Kbuf + (jt & 1) * KSTAGE;

        u64 acc[4][8];
#pragma unroll
        for (int i = 0; i < 4; i++)
#pragma unroll
            for (int j = 0; j < 8; j++) acc[i][j] = 0ull;

#pragma unroll 4
        for (int d4 = 0; d4 < 16; d4++) {
            float4 aq[4];
#pragma unroll
            for (int i = 0; i < 4; i++)
                aq[i] = *(const float4*)&Qs[(i * 32 + ty) * QPAD + d4 * 4];
#pragma unroll
            for (int dd = 0; dd < 4; dd++) {
                const float* bp = &Ks[(d4 * 4 + dd) * 128 + tx * 4];
                ulonglong2 b0 = *(const ulonglong2*)bp;
                ulonglong2 b1 = *(const ulonglong2*)(bp + 32);
                ulonglong2 b2 = *(const ulonglong2*)(bp + 64);
                ulonglong2 b3 = *(const ulonglong2*)(bp + 96);
#pragma unroll
                for (int i = 0; i < 4; i++) {
                    u64 ap = bcast2(f4c(aq[i], dd));
                    acc[i][0] = ffma2(ap, b0.x, acc[i][0]);
                    acc[i][1] = ffma2(ap, b0.y, acc[i][1]);
                    acc[i][2] = ffma2(ap, b1.x, acc[i][2]);
                    acc[i][3] = ffma2(ap, b1.y, acc[i][3]);
                    acc[i][4] = ffma2(ap, b2.x, acc[i][4]);
                    acc[i][5] = ffma2(ap, b2.y, acc[i][5]);
                    acc[i][6] = ffma2(ap, b3.x, acc[i][6]);
                    acc[i][7] = ffma2(ap, b3.y, acc[i][7]);
                }
            }
        }

#pragma unroll
        for (int i = 0; i < 4; i++) {
            float* op = wout + ((size_t)bh * SS + i0 + i * 32 + ty) * SS + j0 + tx * 4;
#pragma unroll
            for (int c = 0; c < 4; c++) {
                float2 p0 = unpk(acc[i][c * 2]), p1 = unpk(acc[i][c * 2 + 1]);
                float4 o4 = make_float4(p0.x * 0.25f, p0.y * 0.25f,
                                        p1.x * 0.25f, p1.y * 0.25f);
                *(float4*)(op + c * 32) = o4;
            }
        }
        __syncthreads();
    }
}

// ---------------------------------------------------------------------------
// Row softmax + threshold prune + L1 renorm, in place (exact fp32 path).
// One warp per row; 2048 floats in 64 regs/lane.
// ---------------------------------------------------------------------------
__global__ __launch_bounds__(256) void softmax_kernel(
    const unsigned char* __restrict__ mask, float* __restrict__ w)
{
    const int lane = threadIdx.x & 31;
    const size_t row = (size_t)blockIdx.x * 8 + (threadIdx.x >> 5);
    const int b = (int)(row >> 15);
    float4* rp = (float4*)(w + row * SS);
    const uchar4* mp = (const uchar4*)(mask + (size_t)b * SS);

    float x[64];
    float mx = -3.0e38f;
#pragma unroll
    for (int v = 0; v < 16; v++) {
        float4 t = rp[lane + v * 32];
        uchar4 m = mp[lane + v * 32];
        x[v * 4 + 0] = m.x ? -1e30f : t.x;
        x[v * 4 + 1] = m.y ? -1e30f : t.y;
        x[v * 4 + 2] = m.z ? -1e30f : t.z;
        x[v * 4 + 3] = m.w ? -1e30f : t.w;
    }
#pragma unroll
    for (int i = 0; i < 64; i++) mx = fmaxf(mx, x[i]);
#pragma unroll
    for (int o = 16; o; o >>= 1) mx = fmaxf(mx, __shfl_xor_sync(0xffffffffu, mx, o));

    float z = 0.f;
#pragma unroll
    for (int i = 0; i < 64; i++) {
        float e = __expf(x[i] - mx);
        x[i] = e;
        z += e;
    }
#pragma unroll
    for (int o = 16; o; o >>= 1) z += __shfl_xor_sync(0xffffffffu, z, o);

    const float cut = 0.01f * z;
    float sk = 0.f;
#pragma unroll
    for (int i = 0; i < 64; i++)
        if (x[i] >= cut) sk += x[i];
#pragma unroll
    for (int o = 16; o; o >>= 1) sk += __shfl_xor_sync(0xffffffffu, sk, o);
    const float inv = sk > 0.f ? 1.f / sk : 0.f;

#pragma unroll
    for (int v = 0; v < 16; v++) {
        float4 o4;
        o4.x = x[v * 4 + 0] >= cut ? x[v * 4 + 0] * inv : 0.f;
        o4.y = x[v * 4 + 1] >= cut ? x[v * 4 + 1] * inv : 0.f;
        o4.z = x[v * 4 + 2] >= cut ? x[v * 4 + 2] * inv : 0.f;
        o4.w = x[v * 4 + 3] >= cut ? x[v * 4 + 3] * inv : 0.f;
        rp[lane + v * 32] = o4;
    }
}

// ---------------------------------------------------------------------------
// PV GEMM: out[b][s][h*64+d] = sum_j W[bh][i][j] * V[bh][j][d].
// Tile 128(M) x 64(N), k-chunk 32, 4x16 micro-tile (rows i*32+ty,
// cols tx*4+{0,16,32,48}). 128 threads, 4 CTAs/SM.
// ---------------------------------------------------------------------------
#define WPAD 36
#define PV_STAGE (128 * WPAD + 32 * 64)     // 6656 floats per stage
#define PV_SMEM (2 * PV_STAGE * 4)          // 53.2 KB

__global__ __launch_bounds__(128, 4) void pv_kernel(
    const float* __restrict__ wts, float* __restrict__ outp)
{
    extern __shared__ float psm[];
    const int tid = threadIdx.x;
    const int tx = tid & 3;            // col base tx*4, chunks +0,+16,+32,+48
    const int ty = tid >> 2;           // 0..31; rows i*32+ty
    const int bh = blockIdx.y;
    const int b = bh >> 4, h = bh & 15;
    const int i0 = blockIdx.x * 128;
    const float* Wp = wts + ((size_t)bh * SS + i0) * SS;
    const float* Vp = g_v + (size_t)bh * SS * HD;

    auto prefetch = [&](int kc, int buf) {
        float* Wt = psm + buf * PV_STAGE;
        float* Vt = Wt + 128 * WPAD;
#pragma unroll
        for (int e = 0; e < 8; e++) {
            int f = e * 128 + tid;
            int r = f >> 3, c4 = f & 7;
            cpa16(&Wt[r * WPAD + c4 * 4], Wp + (size_t)r * SS + kc + c4 * 4);
        }
#pragma unroll
        for (int e = 0; e < 4; e++) {
            int f = e * 128 + tid;
            int j = f >> 4, c4 = f & 15;
            cpa16(&Vt[j * 64 + c4 * 4], Vp + (size_t)(kc + j) * HD + c4 * 4);
        }
        CPA_COMMIT;
    };

    u64 acc[4][8];
#pragma unroll
    for (int i = 0; i < 4; i++)
#pragma unroll
        for (int j = 0; j < 8; j++) acc[i][j] = 0ull;

    prefetch(0, 0);

    for (int it = 0; it < 64; it++) {
        if (it < 63) { prefetch((it + 1) * 32, (it + 1) & 1); CPA_WAIT1; }
        else         { CPA_WAIT0; }
        __syncthreads();
        const float* Wt = psm + (it & 1) * PV_STAGE;
        const float* Vt = Wt + 128 * WPAD;
#pragma unroll
        for (int k4 = 0; k4 < 8; k4++) {
            float4 aw[4];
#pragma unroll
            for (int i = 0; i < 4; i++)
                aw[i] = *(const float4*)&Wt[(i * 32 + ty) * WPAD + k4 * 4];
#pragma unroll
            for (int dd = 0; dd < 4; dd++) {
                const float* bp = &Vt[(k4 * 4 + dd) * 64 + tx * 4];
                ulonglong2 b0 = *(const ulonglong2*)bp;
                ulonglong2 b1 = *(const ulonglong2*)(bp + 16);
                ulonglong2 b2 = *(const ulonglong2*)(bp + 32);
                ulonglong2 b3 = *(const ulonglong2*)(bp + 48);
#pragma unroll
                for (int i = 0; i < 4; i++) {
                    u64 ap = bcast2(f4c(aw[i], dd));
                    acc[i][0] = ffma2(ap, b0.x, acc[i][0]);
                    acc[i][1] = ffma2(ap, b0.y, acc[i][1]);
                    acc[i][2] = ffma2(ap, b1.x, acc[i][2]);
                    acc[i][3] = ffma2(ap, b1.y, acc[i][3]);
                    acc[i][4] = ffma2(ap, b2.x, acc[i][4]);
                    acc[i][5] = ffma2(ap, b2.y, acc[i][5]);
                    acc[i][6] = ffma2(ap, b3.x, acc[i][6]);
                    acc[i][7] = ffma2(ap, b3.y, acc[i][7]);
                }
            }
        }
        __syncthreads();
    }

#pragma unroll
    for (int i = 0; i < 4; i++) {
        int s = i0 + i * 32 + ty;
        float* op = outp + ((size_t)b * SS + s) * HH + h * HD + tx * 4;
#pragma unroll
        for (int c = 0; c < 4; c++) {
            float2 p0 = unpk(acc[i][c * 2]), p1 = unpk(acc[i][c * 2 + 1]);
            float4 o4 = make_float4(p0.x, p0.y, p1.x, p1.y);
            *(float4*)(op + c * 16) = o4;
        }
    }
}

// ---------------------------------------------------------------------------
extern "C" void kernel_launch(void* const* d_in, const int* in_sizes, int n_in,
                              void* d_out, int out_size)
{
    const float* query = (const float*)d_in[0];
    const float* key   = (const float*)d_in[1];
    const float* value = (const float*)d_in[2];
    const unsigned char* mask = (const unsigned char*)d_in[3];
    const float* Wq = (const float*)d_in[4];
    const float* bq = (const float*)d_in[5];
    const float* Wk = (const float*)d_in[6];
    const float* bk = (const float*)d_in[7];
    const float* Wv = (const float*)d_in[8];
    const float* bv = (const float*)d_in[9];

    float* outp = (float*)d_out;                        // [B,S,H]
    float* wts  = outp + (size_t)BB * SS * HH;          // [B,h,S,S]

    float *gq, *gk, *gv, *gkt, *gwt;
    cudaGetSymbolAddress((void**)&gq, g_q);
    cudaGetSymbolAddress((void**)&gk, g_k);
    cudaGetSymbolAddress((void**)&gv, g_v);
    cudaGetSymbolAddress((void**)&gkt, g_kt);
    cudaGetSymbolAddress((void**)&gwt, g_wt);

    cudaFuncSetAttribute(proj_kernel, cudaFuncAttributeMaxDynamicSharedMemorySize,
                         PROJ_SMEM);
    cudaFuncSetAttribute(score_kernel, cudaFuncAttributeMaxDynamicSharedMemorySize,
                         SCORE_SMEM);
    cudaFuncSetAttribute(pv_kernel, cudaFuncAttributeMaxDynamicSharedMemorySize,
                         PV_SMEM);

    dim3 tb(32, 8);

    transpose_w3<<<dim3(32, 32, 3), tb>>>(Wq, Wk, Wv, gwt);

    dim3 pgrid(HH / 128, NROWS / 64, 3);
    proj_kernel<<<pgrid, 128, PROJ_SMEM>>>(query, key, value, gwt, bq, bk, bv, gq, gk, gv);

    dim3 tkgrid(SS / 32, HD / 32, BH);
    transpose_k<<<tkgrid, tb>>>(gk, gkt);

    dim3 sgrid(SS / 128 / 4, SS / 128, BH);
    score_kernel<<<sgrid, 256, SCORE_SMEM>>>(wts);

    softmax_kernel<<<(BH * SS) / 8, 256>>>(mask, wts);

    dim3 vgrid(SS / 128, BH);
    pv_kernel<<<vgrid, 128, PV_SMEM>>>(wts, outp);
}

// round 17
// speedup vs baseline: 1.2716x; 1.0011x over previous
#include <cuda_runtime.h>
#include <math.h>
#include <stdint.h>

#define BB 2
#define SS 2048
#define HH 1024
#define NH 16
#define HD 64
#define BH 32
#define NROWS 4096

// scratch (static __device__ arrays; no runtime allocation)
__device__ float g_q[(size_t)BH * SS * HD];
__device__ float g_k[(size_t)BH * SS * HD];
__device__ float g_v[(size_t)BH * SS * HD];
__device__ float g_kt[(size_t)BH * HD * SS];      // K transposed: [bh][d][s]
__device__ float g_wt[3 * (size_t)HH * HH];       // Wq,Wk,Wv transposed: [k][n]

typedef unsigned long long u64;

// ---- packed fp32x2 helpers (sm_103a FFMA2) ----
__device__ __forceinline__ u64 bcast2(float x) {
    u64 d; unsigned int u = __float_as_uint(x);
    asm("mov.b64 %0, {%1,%2};" : "=l"(d) : "r"(u), "r"(u));
    return d;
}
__device__ __forceinline__ u64 ffma2(u64 a, u64 b, u64 c) {
    u64 d;
    asm("fma.rn.f32x2 %0, %1, %2, %3;" : "=l"(d) : "l"(a), "l"(b), "l"(c));
    return d;
}
__device__ __forceinline__ float2 unpk(u64 v) {
    unsigned int lo, hi;
    asm("mov.b64 {%0,%1}, %2;" : "=r"(lo), "=r"(hi) : "l"(v));
    return make_float2(__uint_as_float(lo), __uint_as_float(hi));
}
__device__ __forceinline__ float f4c(const float4& v, int i) {
    return i == 0 ? v.x : i == 1 ? v.y : i == 2 ? v.z : v.w;
}

// ---- cp.async helpers ----
__device__ __forceinline__ void cpa16(void* s, const void* g) {
    unsigned int sa = (unsigned int)__cvta_generic_to_shared(s);
    asm volatile("cp.async.ca.shared.global [%0], [%1], 16;" :: "r"(sa), "l"(g));
}
#define CPA_COMMIT  asm volatile("cp.async.commit_group;")
#define CPA_WAIT1   asm volatile("cp.async.wait_group 1;")
#define CPA_WAIT0   asm volatile("cp.async.wait_group 0;")

// ---------------------------------------------------------------------------
// Transpose all three W matrices: g_wt[z][k][n] = W_z[n][k]
// ---------------------------------------------------------------------------
__global__ __launch_bounds__(256) void transpose_w3(
    const float* __restrict__ Wq, const float* __restrict__ Wk,
    const float* __restrict__ Wv, float* __restrict__ outp)
{
    __shared__ float t[32][33];
    const int z = blockIdx.z;
    const float* in = z == 0 ? Wq : z == 1 ? Wk : Wv;
    float* op = outp + (size_t)z * HH * HH;
    const int x0 = blockIdx.x * 32, y0 = blockIdx.y * 32;
    const int x = threadIdx.x, y = threadIdx.y;   // 32 x 8
    for (int i = y; i < 32; i += 8) t[i][x] = in[(size_t)(y0 + i) * HH + x0 + x];
    __syncthreads();
    for (int i = y; i < 32; i += 8) op[(size_t)(x0 + i) * HH + y0 + x] = t[x][i];
}

// ---------------------------------------------------------------------------
// Transpose K: [bh][s][d] -> [bh][d][s]
// ---------------------------------------------------------------------------
__global__ __launch_bounds__(256) void transpose_k(
    const float* __restrict__ in, float* __restrict__ outp)
{
    __shared__ float t[32][33];
    const int bh = blockIdx.z;
    const int s0 = blockIdx.x * 32;
    const int d0 = blockIdx.y * 32;
    const int x = threadIdx.x, y = threadIdx.y;   // 32 x 8
    const float* ip = in + ((size_t)bh * SS + s0) * HD + d0;
    for (int i = y; i < 32; i += 8) t[i][x] = ip[(size_t)i * HD + x];
    __syncthreads();
    float* op = outp + ((size_t)bh * HD + d0) * SS + s0;
    for (int i = y; i < 32; i += 8) op[(size_t)i * SS + x] = t[x][i];
}

// ---------------------------------------------------------------------------
// Fused QKV projection GEMM (grid.z selects q/k/v): out = X @ W^T + b,
// scattered to [bh][s][d]. Tile 64(M)x128(N), BK=32, 4x16 FFMA2 micro-tile
// (rows i*16+ty, cols tx*4+{0,32,64,96}). 128 threads, 4 CTAs/SM.
// ---------------------------------------------------------------------------
#define APAD 36
#define PROJ_STAGE (64 * APAD + 32 * 128)    // 6400 floats per stage
#define PROJ_SMEM (2 * PROJ_STAGE * 4)       // 51.2 KB

__global__ __launch_bounds__(128, 4) void proj_kernel(
    const float* __restrict__ Xq, const float* __restrict__ Xk,
    const float* __restrict__ Xv, const float* __restrict__ Wt3,
    const float* __restrict__ bq, const float* __restrict__ bk,
    const float* __restrict__ bv,
    float* __restrict__ oq, float* __restrict__ ok, float* __restrict__ ov)
{
    extern __shared__ float sm[];
    const int z = blockIdx.z;
    const float* X    = z == 0 ? Xq : z == 1 ? Xk : Xv;
    const float* Wt   = Wt3 + (size_t)z * HH * HH;
    const float* bias = z == 0 ? bq : z == 1 ? bk : bv;
    float* outp       = z == 0 ? oq : z == 1 ? ok : ov;

    const int tid = threadIdx.x;
    const int tx = tid & 7;            // col base tx*4, chunks +0,+32,+64,+96
    const int ty = tid >> 3;           // 0..15; rows i*16+ty
    const int i0 = blockIdx.y * 64;
    const int j0 = blockIdx.x * 128;

    auto prefetch = [&](int k0, int buf) {
        float* As = sm + buf * PROJ_STAGE;
        float* Bs = As + 64 * APAD;
#pragma unroll
        for (int e = 0; e < 4; e++) {
            int f = e * 128 + tid;
            int r = f >> 3, c4 = f & 7;
            cpa16(&As[r * APAD + c4 * 4], X + (size_t)(i0 + r) * HH + k0 + c4 * 4);
        }
#pragma unroll
        for (int e = 0; e < 8; e++) {
            int f = e * 128 + tid;
            int k = f >> 5, c = f & 31;
            cpa16(&Bs[k * 128 + c * 4], Wt + (size_t)(k0 + k) * HH + j0 + c * 4);
        }
        CPA_COMMIT;
    };

    u64 acc[4][8];
#pragma unroll
    for (int i = 0; i < 4; i++)
#pragma unroll
        for (int j = 0; j < 8; j++) acc[i][j] = 0ull;

    prefetch(0, 0);

    for (int it = 0; it < 32; it++) {
        if (it < 31) { prefetch((it + 1) * 32, (it + 1) & 1); CPA_WAIT1; }
        else         { CPA_WAIT0; }
        __syncthreads();
        const float* As = sm + (it & 1) * PROJ_STAGE;
        const float* Bs = As + 64 * APAD;
#pragma unroll
        for (int k4 = 0; k4 < 8; k4++) {
            float4 aq[4];
#pragma unroll
            for (int i = 0; i < 4; i++)
                aq[i] = *(const float4*)&As[(i * 16 + ty) * APAD + k4 * 4];
#pragma unroll
            for (int dd = 0; dd < 4; dd++) {
                const float* bp = &Bs[(k4 * 4 + dd) * 128 + tx * 4];
                ulonglong2 b0 = *(const ulonglong2*)bp;
                ulonglong2 b1 = *(const ulonglong2*)(bp + 32);
                ulonglong2 b2 = *(const ulonglong2*)(bp + 64);
                ulonglong2 b3 = *(const ulonglong2*)(bp + 96);
#pragma unroll
                for (int i = 0; i < 4; i++) {
                    u64 ap = bcast2(f4c(aq[i], dd));
                    acc[i][0] = ffma2(ap, b0.x, acc[i][0]);
                    acc[i][1] = ffma2(ap, b0.y, acc[i][1]);
                    acc[i][2] = ffma2(ap, b1.x, acc[i][2]);
                    acc[i][3] = ffma2(ap, b1.y, acc[i][3]);
                    acc[i][4] = ffma2(ap, b2.x, acc[i][4]);
                    acc[i][5] = ffma2(ap, b2.y, acc[i][5]);
                    acc[i][6] = ffma2(ap, b3.x, acc[i][6]);
                    acc[i][7] = ffma2(ap, b3.y, acc[i][7]);
                }
            }
        }
        __syncthreads();
    }

#pragma unroll
    for (int c = 0; c < 4; c++) {
        const int col = j0 + tx * 4 + c * 32;
        const int h = col >> 6, d = col & 63;
        float4 bb = *(const float4*)(bias + col);
#pragma unroll
        for (int i = 0; i < 4; i++) {
            int r = i0 + i * 16 + ty;
            int b = r >> 11, s = r & 2047;
            float2 p0 = unpk(acc[i][c * 2]), p1 = unpk(acc[i][c * 2 + 1]);
            float4 o4 = make_float4(p0.x + bb.x, p0.y + bb.y, p1.x + bb.z, p1.y + bb.w);
            *(float4*)(outp + (((size_t)(b * NH + h)) * SS + s) * HD + d) = o4;
        }
    }
}

// ---------------------------------------------------------------------------
// Score GEMM: wout[bh][i][j] = 0.25 * sum_d q[i,d]*k[j,d].
// Block = 128 i-rows x (4 consecutive 128-wide j-tiles). 4x16 micro-tile
// (rows i*32+ty, cols tx*4+{0,32,64,96}). 2 CTAs/SM (128-reg cap).
// ---------------------------------------------------------------------------
#define QPAD 68
#define KSTAGE (64 * 128)
#define SCORE_SMEM ((128 * QPAD + 2 * KSTAGE) * 4)

__global__ __launch_bounds__(256, 2) void score_kernel(float* __restrict__ wout)
{
    extern __shared__ float sm[];
    float* Qs = sm;                       // [128][QPAD]
    float* Kbuf = sm + 128 * QPAD;        // 2 x [64][128]
    const int tid = threadIdx.x;
    const int tx = tid & 7;               // col base tx*4, chunks +0,+32,+64,+96
    const int ty = tid >> 3;              // 0..31; rows i*32+ty
    const int bh = blockIdx.z;
    const int i0 = blockIdx.y * 128;
    const int jb0 = blockIdx.x * 4;

    const float* Qp = g_q + ((size_t)bh * SS + i0) * HD;
    const float* Ktp = g_kt + (size_t)bh * HD * SS;

#pragma unroll
    for (int e = 0; e < 8; e++) {
        int f = e * 256 + tid;
        int r = f >> 4, c4 = f & 15;
        cpa16(&Qs[r * QPAD + c4 * 4], Qp + (size_t)r * HD + c4 * 4);
    }
    CPA_COMMIT;

    auto prefetchK = [&](int j0, int buf) {
        float* Ks = Kbuf + buf * KSTAGE;
#pragma unroll
        for (int e = 0; e < 8; e++) {
            int f = e * 256 + tid;
            int d = f >> 5, c = f & 31;
            cpa16(&Ks[d * 128 + c * 4], Ktp + (size_t)d * SS + j0 + c * 4);
        }
        CPA_COMMIT;
    };
    prefetchK(jb0 * 128, 0);

    for (int jt = 0; jt < 4; jt++) {
        const int j0 = (jb0 + jt) * 128;
        if (jt < 3) { prefetchK(j0 + 128, (jt + 1) & 1); CPA_WAIT1; }
        else        { CPA_WAIT0; }
        __syncthreads();
        const float* Ks = Kbuf + (jt & 1) * KSTAGE;

        u64 acc[4][8];
#pragma unroll
        for (int i = 0; i < 4; i++)
#pragma unroll
            for (int j = 0; j < 8; j++) acc[i][j] = 0ull;

#pragma unroll 4
        for (int d4 = 0; d4 < 16; d4++) {
            float4 aq[4];
#pragma unroll
            for (int i = 0; i < 4; i++)
                aq[i] = *(const float4*)&Qs[(i * 32 + ty) * QPAD + d4 * 4];
#pragma unroll
            for (int dd = 0; dd < 4; dd++) {
                const float* bp = &Ks[(d4 * 4 + dd) * 128 + tx * 4];
                ulonglong2 b0 = *(const ulonglong2*)bp;
                ulonglong2 b1 = *(const ulonglong2*)(bp + 32);
                ulonglong2 b2 = *(const ulonglong2*)(bp + 64);
                ulonglong2 b3 = *(const ulonglong2*)(bp + 96);
#pragma unroll
                for (int i = 0; i < 4; i++) {
                    u64 ap = bcast2(f4c(aq[i], dd));
                    acc[i][0] = ffma2(ap, b0.x, acc[i][0]);
                    acc[i][1] = ffma2(ap, b0.y, acc[i][1]);
                    acc[i][2] = ffma2(ap, b1.x, acc[i][2]);
                    acc[i][3] = ffma2(ap, b1.y, acc[i][3]);
                    acc[i][4] = ffma2(ap, b2.x, acc[i][4]);
                    acc[i][5] = ffma2(ap, b2.y, acc[i][5]);
                    acc[i][6] = ffma2(ap, b3.x, acc[i][6]);
                    acc[i][7] = ffma2(ap, b3.y, acc[i][7]);
                }
            }
        }

#pragma unroll
        for (int i = 0; i < 4; i++) {
            float* op = wout + ((size_t)bh * SS + i0 + i * 32 + ty) * SS + j0 + tx * 4;
#pragma unroll
            for (int c = 0; c < 4; c++) {
                float2 p0 = unpk(acc[i][c * 2]), p1 = unpk(acc[i][c * 2 + 1]);
                float4 o4 = make_float4(p0.x * 0.25f, p0.y * 0.25f,
                                        p1.x * 0.25f, p1.y * 0.25f);
                *(float4*)(op + c * 32) = o4;
            }
        }
        __syncthreads();
    }
}

// ---------------------------------------------------------------------------
// Row softmax + threshold prune + L1 renorm, in place (exact fp32 path).
// One warp per row; 2048 floats in 64 regs/lane.
// ---------------------------------------------------------------------------
__global__ __launch_bounds__(256) void softmax_kernel(
    const unsigned char* __restrict__ mask, float* __restrict__ w)
{
    const int lane = threadIdx.x & 31;
    const size_t row = (size_t)blockIdx.x * 8 + (threadIdx.x >> 5);
    const int b = (int)(row >> 15);
    float4* rp = (float4*)(w + row * SS);
    const uchar4* mp = (const uchar4*)(mask + (size_t)b * SS);

    float x[64];
    float mx = -3.0e38f;
#pragma unroll
    for (int v = 0; v < 16; v++) {
        float4 t = rp[lane + v * 32];
        uchar4 m = mp[lane + v * 32];
        x[v * 4 + 0] = m.x ? -1e30f : t.x;
        x[v * 4 + 1] = m.y ? -1e30f : t.y;
        x[v * 4 + 2] = m.z ? -1e30f : t.z;
        x[v * 4 + 3] = m.w ? -1e30f : t.w;
    }
#pragma unroll
    for (int i = 0; i < 64; i++) mx = fmaxf(mx, x[i]);
#pragma unroll
    for (int o = 16; o; o >>= 1) mx = fmaxf(mx, __shfl_xor_sync(0xffffffffu, mx, o));

    float z = 0.f;
#pragma unroll
    for (int i = 0; i < 64; i++) {
        float e = __expf(x[i] - mx);
        x[i] = e;
        z += e;
    }
#pragma unroll
    for (int o = 16; o; o >>= 1) z += __shfl_xor_sync(0xffffffffu, z, o);

    const float cut = 0.01f * z;
    float sk = 0.f;
#pragma unroll
    for (int i = 0; i < 64; i++)
        if (x[i] >= cut) sk += x[i];
#pragma unroll
    for (int o = 16; o; o >>= 1) sk += __shfl_xor_sync(0xffffffffu, sk, o);
    const float inv = sk > 0.f ? 1.f / sk : 0.f;

#pragma unroll
    for (int v = 0; v < 16; v++) {
        float4 o4;
        o4.x = x[v * 4 + 0] >= cut ? x[v * 4 + 0] * inv : 0.f;
        o4.y = x[v * 4 + 1] >= cut ? x[v * 4 + 1] * inv : 0.f;
        o4.z = x[v * 4 + 2] >= cut ? x[v * 4 + 2] * inv : 0.f;
        o4.w = x[v * 4 + 3] >= cut ? x[v * 4 + 3] * inv : 0.f;
        rp[lane + v * 32] = o4;
    }
}

// ---------------------------------------------------------------------------
// PV GEMM: out[b][s][h*64+d] = sum_j W[bh][i][j] * V[bh][j][d].
// Tile 128(M) x 64(N), k-chunk 32, 4x16 micro-tile (rows i*32+ty,
// cols tx*4+{0,16,32,48}). 128 threads, 4 CTAs/SM.
// ---------------------------------------------------------------------------
#define WPAD 36
#define PV_STAGE (128 * WPAD + 32 * 64)     // 6656 floats per stage
#define PV_SMEM (2 * PV_STAGE * 4)          // 53.2 KB

__global__ __launch_bounds__(128, 4) void pv_kernel(
    const float* __restrict__ wts, float* __restrict__ outp)
{
    extern __shared__ float psm[];
    const int tid = threadIdx.x;
    const int tx = tid & 3;            // col base tx*4, chunks +0,+16,+32,+48
    const int ty = tid >> 2;           // 0..31; rows i*32+ty
    const int bh = blockIdx.y;
    const int b = bh >> 4, h = bh & 15;
    const int i0 = blockIdx.x * 128;
    const float* Wp = wts + ((size_t)bh * SS + i0) * SS;
    const float* Vp = g_v + (size_t)bh * SS * HD;

    auto prefetch = [&](int kc, int buf) {
        float* Wt = psm + buf * PV_STAGE;
        float* Vt = Wt + 128 * WPAD;
#pragma unroll
        for (int e = 0; e < 8; e++) {
            int f = e * 128 + tid;
            int r = f >> 3, c4 = f & 7;
            cpa16(&Wt[r * WPAD + c4 * 4], Wp + (size_t)r * SS + kc + c4 * 4);
        }
#pragma unroll
        for (int e = 0; e < 4; e++) {
            int f = e * 128 + tid;
            int j = f >> 4, c4 = f & 15;
            cpa16(&Vt[j * 64 + c4 * 4], Vp + (size_t)(kc + j) * HD + c4 * 4);
        }
        CPA_COMMIT;
    };

    u64 acc[4][8];
#pragma unroll
    for (int i = 0; i < 4; i++)
#pragma unroll
        for (int j = 0; j < 8; j++) acc[i][j] = 0ull;

    prefetch(0, 0);

    for (int it = 0; it < 64; it++) {
        if (it < 63) { prefetch((it + 1) * 32, (it + 1) & 1); CPA_WAIT1; }
        else         { CPA_WAIT0; }
        __syncthreads();
        const float* Wt = psm + (it & 1) * PV_STAGE;
        const float* Vt = Wt + 128 * WPAD;
#pragma unroll
        for (int k4 = 0; k4 < 8; k4++) {
            float4 aw[4];
#pragma unroll
            for (int i = 0; i < 4; i++)
                aw[i] = *(const float4*)&Wt[(i * 32 + ty) * WPAD + k4 * 4];
#pragma unroll
            for (int dd = 0; dd < 4; dd++) {
                const float* bp = &Vt[(k4 * 4 + dd) * 64 + tx * 4];
                ulonglong2 b0 = *(const ulonglong2*)bp;
                ulonglong2 b1 = *(const ulonglong2*)(bp + 16);
                ulonglong2 b2 = *(const ulonglong2*)(bp + 32);
                ulonglong2 b3 = *(const ulonglong2*)(bp + 48);
#pragma unroll
                for (int i = 0; i < 4; i++) {
                    u64 ap = bcast2(f4c(aw[i], dd));
                    acc[i][0] = ffma2(ap, b0.x, acc[i][0]);
                    acc[i][1] = ffma2(ap, b0.y, acc[i][1]);
                    acc[i][2] = ffma2(ap, b1.x, acc[i][2]);
                    acc[i][3] = ffma2(ap, b1.y, acc[i][3]);
                    acc[i][4] = ffma2(ap, b2.x, acc[i][4]);
                    acc[i][5] = ffma2(ap, b2.y, acc[i][5]);
                    acc[i][6] = ffma2(ap, b3.x, acc[i][6]);
                    acc[i][7] = ffma2(ap, b3.y, acc[i][7]);
                }
            }
        }
        __syncthreads();
    }

#pragma unroll
    for (int i = 0; i < 4; i++) {
        int s = i0 + i * 32 + ty;
        float* op = outp + ((size_t)b * SS + s) * HH + h * HD + tx * 4;
#pragma unroll
        for (int c = 0; c < 4; c++) {
            float2 p0 = unpk(acc[i][c * 2]), p1 = unpk(acc[i][c * 2 + 1]);
            float4 o4 = make_float4(p0.x, p0.y, p1.x, p1.y);
            *(float4*)(op + c * 16) = o4;
        }
    }
}

// ---------------------------------------------------------------------------
extern "C" void kernel_launch(void* const* d_in, const int* in_sizes, int n_in,
                              void* d_out, int out_size)
{
    const float* query = (const float*)d_in[0];
    const float* key   = (const float*)d_in[1];
    const float* value = (const float*)d_in[2];
    const unsigned char* mask = (const unsigned char*)d_in[3];
    const float* Wq = (const float*)d_in[4];
    const float* bq = (const float*)d_in[5];
    const float* Wk = (const float*)d_in[6];
    const float* bk = (const float*)d_in[7];
    const float* Wv = (const float*)d_in[8];
    const float* bv = (const float*)d_in[9];

    float* outp = (float*)d_out;                        // [B,S,H]
    float* wts  = outp + (size_t)BB * SS * HH;          // [B,h,S,S]

    float *gq, *gk, *gv, *gkt, *gwt;
    cudaGetSymbolAddress((void**)&gq, g_q);
    cudaGetSymbolAddress((void**)&gk, g_k);
    cudaGetSymbolAddress((void**)&gv, g_v);
    cudaGetSymbolAddress((void**)&gkt, g_kt);
    cudaGetSymbolAddress((void**)&gwt, g_wt);

    cudaFuncSetAttribute(proj_kernel, cudaFuncAttributeMaxDynamicSharedMemorySize,
                         PROJ_SMEM);
    cudaFuncSetAttribute(score_kernel, cudaFuncAttributeMaxDynamicSharedMemorySize,
                         SCORE_SMEM);
    cudaFuncSetAttribute(pv_kernel, cudaFuncAttributeMaxDynamicSharedMemorySize,
                         PV_SMEM);

    dim3 tb(32, 8);

    transpose_w3<<<dim3(32, 32, 3), tb>>>(Wq, Wk, Wv, gwt);

    dim3 pgrid(HH / 128, NROWS / 64, 3);
    proj_kernel<<<pgrid, 128, PROJ_SMEM>>>(query, key, value, gwt, bq, bk, bv, gq, gk, gv);

    dim3 tkgrid(SS / 32, HD / 32, BH);
    transpose_k<<<tkgrid, tb>>>(gk, gkt);

    dim3 sgrid(SS / 128 / 4, SS / 128, BH);
    score_kernel<<<sgrid, 256, SCORE_SMEM>>>(wts);

    softmax_kernel<<<(BH * SS) / 8, 256>>>(mask, wts);

    dim3 vgrid(SS / 128, BH);
    pv_kernel<<<vgrid, 128, PV_SMEM>>>(wts, outp);
}